// round 13
// baseline (speedup 1.0000x reference)
#include <cuda_runtime.h>
#include <cuda_bf16.h>
#include <cuda_fp16.h>
#include <cstdint>

typedef __nv_bfloat16 bf16;

// ---------------------------------------------------------------------------
static __device__ __forceinline__ uint32_t smem_u32(const void* p) {
    uint32_t a;
    asm("{ .reg .u64 t; cvta.to.shared.u64 t, %1; cvt.u32.u64 %0, t; }" : "=r"(a) : "l"(p));
    return a;
}
static __device__ __forceinline__ void mma16816(float* c, const uint32_t* a, const uint32_t* b) {
    asm volatile("mma.sync.aligned.m16n8k16.row.col.f32.bf16.bf16.f32 "
        "{%0,%1,%2,%3}, {%4,%5,%6,%7}, {%8,%9}, {%0,%1,%2,%3};"
        : "+f"(c[0]), "+f"(c[1]), "+f"(c[2]), "+f"(c[3])
        : "r"(a[0]), "r"(a[1]), "r"(a[2]), "r"(a[3]), "r"(b[0]), "r"(b[1]));
}
static __device__ __forceinline__ void mma16816h(float* c, const uint32_t* a, const uint32_t* b) {
    asm volatile("mma.sync.aligned.m16n8k16.row.col.f32.f16.f16.f32 "
        "{%0,%1,%2,%3}, {%4,%5,%6,%7}, {%8,%9}, {%0,%1,%2,%3};"
        : "+f"(c[0]), "+f"(c[1]), "+f"(c[2]), "+f"(c[3])
        : "r"(a[0]), "r"(a[1]), "r"(a[2]), "r"(a[3]), "r"(b[0]), "r"(b[1]));
}
static __device__ __forceinline__ void mma3(float* c, const uint32_t* ah, const uint32_t* al,
                                            const uint32_t* bh, const uint32_t* bl) {
    mma16816(c, ah, bh); mma16816(c, ah, bl); mma16816(c, al, bh);
}
static __device__ __forceinline__ void ldsm4(uint32_t* r, uint32_t a) {
    asm volatile("ldmatrix.sync.aligned.m8n8.x4.shared.b16 {%0,%1,%2,%3}, [%4];"
        : "=r"(r[0]), "=r"(r[1]), "=r"(r[2]), "=r"(r[3]) : "r"(a));
}
static __device__ __forceinline__ void ldsmA(uint32_t* r, uint32_t base, int m0, int k0, int sbytes, int lane) {
    ldsm4(r, base + (uint32_t)((m0 + (lane & 7) + ((lane >> 3) & 1) * 8) * sbytes
                               + (k0 + ((lane >> 4) << 3)) * 2));
}
static __device__ __forceinline__ void ldsmB(uint32_t* r, uint32_t base, int n0, int k0, int sbytes, int lane) {
    ldsm4(r, base + (uint32_t)((n0 + (lane & 7) + ((lane >> 4) << 3)) * sbytes
                               + (k0 + (((lane >> 3) & 1) << 3)) * 2));
}
#define CP16(sm_, gp_) asm volatile("cp.async.cg.shared.global [%0], [%1], 16;" :: "r"(sm_), "l"(gp_))
#define CPCOMMIT()     asm volatile("cp.async.commit_group;")
#define CPWAIT(n)      asm volatile("cp.async.wait_group %0;" :: "n"(n))

static __device__ __forceinline__ void store_split2(bf16* Ch, bf16* Cl, long off, float x, float y) {
    __align__(4) bf16 h[2] = {__float2bfloat16(x), __float2bfloat16(y)};
    __align__(4) bf16 l[2] = {__float2bfloat16(x - __bfloat162float(h[0])),
                              __float2bfloat16(y - __bfloat162float(h[1]))};
    *(uint32_t*)(Ch + off) = *(uint32_t*)h;
    *(uint32_t*)(Cl + off) = *(uint32_t*)l;
}
static __device__ __forceinline__ uint32_t pack_h2(float x, float y) {
    __half2 h = __floats2half2_rn(x, y);
    return *(uint32_t*)&h;
}

// ---------------- scratch ----------------
__device__ bf16 g_qh[4194304], g_ql[4194304];
__device__ bf16 g_xh[4194304], g_xl[4194304];
__device__ bf16 g_wqh[1048576], g_wql[1048576];
__device__ bf16 g_wkh[1048576], g_wkl[1048576];
__device__ bf16 g_wvh[1048576], g_wvl[1048576];
__device__ bf16 g_woh[1048576], g_wol[1048576];
__device__ bf16 g_Qh[4194304], g_Ql[4194304];
__device__ bf16 g_Kh[4194304], g_Kl[4194304];
__device__ bf16 g_Vh[4194304], g_Vl[4194304];
__device__ __half g_Vth16[4194304], g_Vtl16[4194304];   // V^T fp16 hi/lo
__device__ bf16 g_Bh[4194304], g_Bl[4194304];
__device__ float g_attn[134217728];

// ---------------- merged fp32 -> bf16 hi/lo for all 6 tensors ----------------
__global__ __launch_bounds__(256) void cvt_all(
    const float* __restrict__ s0, const float* __restrict__ s1,
    const float* __restrict__ s2, const float* __restrict__ s3,
    const float* __restrict__ s4, const float* __restrict__ s5,
    bf16* __restrict__ h0, bf16* __restrict__ l0, bf16* __restrict__ h1, bf16* __restrict__ l1,
    bf16* __restrict__ h2, bf16* __restrict__ l2, bf16* __restrict__ h3, bf16* __restrict__ l3,
    bf16* __restrict__ h4, bf16* __restrict__ l4, bf16* __restrict__ h5, bf16* __restrict__ l5)
{
    long i = (long)blockIdx.x * 256 + threadIdx.x;   // < 3145728
    const float* src; bf16 *h, *l; long li;
    if (i < 1048576)      { src = s0; h = h0; l = l0; li = i; }
    else if (i < 2097152) { src = s1; h = h1; l = l1; li = i - 1048576; }
    else {
        long j = i - 2097152;
        int w = (int)(j >> 18);
        li = j & 262143;
        src = (w == 0) ? s2 : (w == 1) ? s3 : (w == 2) ? s4 : s5;
        h   = (w == 0) ? h2 : (w == 1) ? h3 : (w == 2) ? h4 : h5;
        l   = (w == 0) ? l2 : (w == 1) ? l3 : (w == 2) ? l4 : l5;
    }
    float4 v = ((const float4*)src)[li];
    float f[4] = {v.x, v.y, v.z, v.w};
    __align__(8) bf16 hv[4], lv[4];
#pragma unroll
    for (int j = 0; j < 4; j++) {
        hv[j] = __float2bfloat16(f[j]);
        lv[j] = __float2bfloat16(f[j] - __bfloat162float(hv[j]));
    }
    ((uint2*)h)[li] = *(uint2*)hv;
    ((uint2*)l)[li] = *(uint2*)lv;
}

// ---------------------------------------------------------------------------
// hgemm body (unchanged, proven)
// ---------------------------------------------------------------------------
static __device__ __forceinline__ void hgemm_body(
    const bf16* __restrict__ Ah, const bf16* __restrict__ Al,
    const bf16* __restrict__ Bh, const bf16* __restrict__ Bl,
    const float* __restrict__ bias, float* __restrict__ Cf,
    bf16* __restrict__ Ch, bf16* __restrict__ Cl,
    int K, int lda, int ldb, int ldc, char* sm)
{
    uint32_t sb = smem_u32(sm);
    int t = threadIdx.x, lane = t & 31, wid = t >> 5;
    int wm = wid & 3, wn = wid >> 2;
    long m0 = blockIdx.y * 128, n0 = blockIdx.x * 128;

    const bf16* g0 = Ah + m0 * lda;
    const bf16* g1 = Al + m0 * lda;
    const bf16* g2 = Bh + n0 * ldb;
    const bf16* g3 = Bl + n0 * ldb;

#define G_ISSUE(c_, buf_) do {                                                  \
    int _c = (c_); uint32_t _bs = sb + (buf_) * 40960;                          \
    _Pragma("unroll")                                                           \
    for (int i = 0; i < 8; i++) {                                               \
        const int tile = i >> 1;                                                \
        int w = t + 256 * (i & 1);                                               \
        int row = w >> 2, sg = w & 3;                                           \
        const bf16* gp = (tile == 0 ? g0 : tile == 1 ? g1 : tile == 2 ? g2 : g3)\
            + (long)row * (tile < 2 ? lda : ldb) + _c * 32 + sg * 8;            \
        CP16(_bs + tile * 10240 + row * 80 + sg * 16, gp);                      \
    }                                                                           \
    CPCOMMIT();                                                                 \
} while (0)

    float acc[2][8][4] = {};
    int nc = K >> 5;
    G_ISSUE(0, 0);
    G_ISSUE(1, 1);
    for (int c = 0; c < nc; c++) {
        if (c + 1 < nc) { CPWAIT(1); } else { CPWAIT(0); }
        __syncthreads();
        uint32_t bAh = sb + (c & 1) * 40960, bAl = bAh + 10240;
        uint32_t bBh = bAh + 20480, bBl = bAh + 30720;
#pragma unroll
        for (int k0 = 0; k0 < 32; k0 += 16) {
            uint32_t ah[2][4], al[2][4], bhf[4][4], blf[4][4];
#pragma unroll
            for (int mt = 0; mt < 2; mt++) {
                ldsmA(ah[mt], bAh, wm * 32 + mt * 16, k0, 80, lane);
                ldsmA(al[mt], bAl, wm * 32 + mt * 16, k0, 80, lane);
            }
#pragma unroll
            for (int p = 0; p < 4; p++) {
                ldsmB(bhf[p], bBh, wn * 64 + p * 16, k0, 80, lane);
                ldsmB(blf[p], bBl, wn * 64 + p * 16, k0, 80, lane);
            }
#pragma unroll
            for (int mt = 0; mt < 2; mt++)
#pragma unroll
                for (int p = 0; p < 4; p++) {
                    mma3(acc[mt][p * 2],     ah[mt], al[mt], &bhf[p][0], &blf[p][0]);
                    mma3(acc[mt][p * 2 + 1], ah[mt], al[mt], &bhf[p][2], &blf[p][2]);
                }
        }
        __syncthreads();
        if (c + 2 < nc) G_ISSUE(c + 2, c & 1);
    }
#undef G_ISSUE

#pragma unroll
    for (int mt = 0; mt < 2; mt++)
#pragma unroll
        for (int nt = 0; nt < 8; nt++) {
            float* cc = acc[mt][nt];
            long r0 = m0 + wm * 32 + mt * 16 + (lane >> 2);
            int col = (int)n0 + wn * 64 + nt * 8 + 2 * (lane & 3);
            float b0 = bias[col], b1 = bias[col + 1];
            float f0 = cc[0] + b0, f1 = cc[1] + b1, f2 = cc[2] + b0, f3 = cc[3] + b1;
            if (Cf) {
                *(float2*)(Cf + r0 * ldc + col) = make_float2(f0, f1);
                *(float2*)(Cf + (r0 + 8) * ldc + col) = make_float2(f2, f3);
            }
            if (Ch) {
                store_split2(Ch, Cl, r0 * ldc + col, f0, f1);
                store_split2(Ch, Cl, (r0 + 8) * ldc + col, f2, f3);
            }
        }
}

__global__ __launch_bounds__(256) void proj3(
    const bf16* __restrict__ qh, const bf16* __restrict__ ql,
    const bf16* __restrict__ xh, const bf16* __restrict__ xl,
    const bf16* __restrict__ wqh, const bf16* __restrict__ wql,
    const bf16* __restrict__ wkh, const bf16* __restrict__ wkl,
    const bf16* __restrict__ wvh, const bf16* __restrict__ wvl,
    const float* __restrict__ bq, const float* __restrict__ bk, const float* __restrict__ bv,
    bf16* __restrict__ Qh, bf16* __restrict__ Ql,
    bf16* __restrict__ Kh, bf16* __restrict__ Kl,
    bf16* __restrict__ Vh, bf16* __restrict__ Vl)
{
    extern __shared__ char sm[];
    int z = blockIdx.z;
    const bf16* Ah = (z == 0) ? qh : xh;
    const bf16* Al = (z == 0) ? ql : xl;
    const bf16* Bh = (z == 0) ? wqh : (z == 1) ? wkh : wvh;
    const bf16* Bl = (z == 0) ? wql : (z == 1) ? wkl : wvl;
    const float* bias = (z == 0) ? bq : (z == 1) ? bk : bv;
    bf16* Ch = (z == 0) ? Qh : (z == 1) ? Kh : Vh;
    bf16* Cl = (z == 0) ? Ql : (z == 1) ? Kl : Vl;
    hgemm_body(Ah, Al, Bh, Bl, bias, nullptr, Ch, Cl, 1024, 1024, 1024, 1024, sm);
}

__global__ __launch_bounds__(256) void hgemm_out(
    const bf16* __restrict__ Ah, const bf16* __restrict__ Al,
    const bf16* __restrict__ Bh, const bf16* __restrict__ Bl,
    const float* __restrict__ bias, float* __restrict__ Cf)
{
    extern __shared__ char sm[];
    hgemm_body(Ah, Al, Bh, Bl, bias, Cf, nullptr, nullptr, 1024, 1024, 1024, 1024, sm);
}

// ---------------------------------------------------------------------------
// vtrans: V bf16 hi+lo -> per (b,h) [64 d][2048 tok], fp16 hi/lo split
// ---------------------------------------------------------------------------
__global__ __launch_bounds__(256) void vtrans(
    const bf16* __restrict__ Vh, const bf16* __restrict__ Vl,
    __half* __restrict__ Th, __half* __restrict__ Tl) {
    __shared__ bf16 sh[64][72], sl[64][72];
    int t = threadIdx.x, tt = blockIdx.x, bh = blockIdx.y;
    int b = bh >> 4, h = bh & 15;
    const bf16* srch = Vh + ((long)b * 2048 + tt * 64) * 1024 + h * 64;
    const bf16* srcl = Vl + ((long)b * 2048 + tt * 64) * 1024 + h * 64;
#pragma unroll
    for (int i = 0; i < 2; i++) {
        int s = t + 256 * i, row = s >> 3, seg = s & 7;
        *(uint4*)&sh[row][seg * 8] = *(const uint4*)(srch + (long)row * 1024 + seg * 8);
        *(uint4*)&sl[row][seg * 8] = *(const uint4*)(srcl + (long)row * 1024 + seg * 8);
    }
    __syncthreads();
    __half* dh = Th + (long)bh * 64 * 2048 + tt * 64;
    __half* dl = Tl + (long)bh * 64 * 2048 + tt * 64;
#pragma unroll
    for (int i = 0; i < 2; i++) {
        int s = t + 256 * i, d = s >> 3, seg = s & 7;
        __align__(16) __half th[8], tl[8];
#pragma unroll
        for (int j = 0; j < 8; j++) {
            float f = __bfloat162float(sh[seg * 8 + j][d]) + __bfloat162float(sl[seg * 8 + j][d]);
            __half hv = __float2half_rn(f);
            th[j] = hv;
            tl[j] = __float2half_rn(f - __half2float(hv));
        }
        *(uint4*)(dh + (long)d * 2048 + seg * 8) = *(uint4*)th;
        *(uint4*)(dl + (long)d * 2048 + seg * 8) = *(uint4*)tl;
    }
}

// ---------------------------------------------------------------------------
// fused_attn: 256 threads, warp grid 4m x 2n (warp tile 16q x 32k), 2 CTAs/SM.
// P stays in REGISTERS (QK C-frag == PV A-frag); V double-buffered+prefetched;
// ONE __syncthreads per tile; O accumulated as per-warp partials, reduced once.
// smem: Q hi@0 lo@9216 | K buf b@18432+b*18432 (hi,lo) | V buf b@55296+b*18432
//       part@92160 (128f) invs@92672 (64f) ; O-reduce scratch reuses @0 (34KB)
// ---------------------------------------------------------------------------
#define FQ_H  0
#define FQ_L  9216
#define FKBUF(b) (18432 + (b) * 18432)
#define FVBUF(b) (55296 + (b) * 18432)
#define FPART 92160
#define FINVS 92672
#define SM_FUSED 92928

__global__ __launch_bounds__(256, 2) void fused_attn(
    const bf16* __restrict__ Qh, const bf16* __restrict__ Ql,
    const bf16* __restrict__ Kh, const bf16* __restrict__ Kl,
    const __half* __restrict__ Vth, const __half* __restrict__ Vtl,
    const float* __restrict__ mask,
    float* __restrict__ A, bf16* __restrict__ Bh, bf16* __restrict__ Bl)
{
    extern __shared__ char sm[];
    uint32_t sb = smem_u32(sm);
    int t = threadIdx.x, lane = t & 31, wid = t >> 5;
    int wm = wid & 3, wn = wid >> 2;          // 4m x 2n; warp tile 16q x 32k
    int qt = blockIdx.x, bh = blockIdx.y;
    int b = bh >> 4, h = bh & 15;

    const bf16* qh = Qh + ((long)b * 2048 + qt * 64) * 1024 + h * 64;
    const bf16* ql = Ql + ((long)b * 2048 + qt * 64) * 1024 + h * 64;
    const bf16* kh = Kh + (long)b * 2048 * 1024 + h * 64;
    const bf16* kl = Kl + (long)b * 2048 * 1024 + h * 64;
    const __half* vth = Vth + (long)bh * 64 * 2048;
    const __half* vtl = Vtl + (long)bh * 64 * 2048;
    float* Abh = A + ((long)bh * 2048 + qt * 64) * 2048;
    const float* mrow = mask + (long)b * 2048;

    float* part = (float*)(sm + FPART);
    float* invs = (float*)(sm + FINVS);

#define KISSUE(kt_, buf_) do {                                                   \
    int _kt = (kt_); uint32_t _kb = sb + FKBUF(buf_);                            \
    _Pragma("unroll")                                                            \
    for (int i = 0; i < 4; i++) {                                                \
        int w = t + 256 * i;                                                     \
        int tile = w >> 9, inner = w & 511;                                      \
        int row = inner >> 3, sg = inner & 7;                                    \
        const bf16* src = (tile ? kl : kh) + (long)(_kt * 64 + row) * 1024 + sg * 8; \
        CP16(_kb + tile * 9216 + row * 144 + sg * 16, src);                      \
    }                                                                            \
    CPCOMMIT();                                                                  \
} while (0)

#define VISSUE(kt_, buf_) do {                                                   \
    int _kt = (kt_); uint32_t _vb = sb + FVBUF(buf_);                            \
    _Pragma("unroll")                                                            \
    for (int i = 0; i < 4; i++) {                                                \
        int w = t + 256 * i;                                                     \
        int tile = w >> 9, inner = w & 511;                                      \
        int row = inner >> 3, sg = inner & 7;                                    \
        const __half* src = (tile ? vtl : vth) + (long)row * 2048 + _kt * 64 + sg * 8; \
        CP16(_vb + tile * 9216 + row * 144 + sg * 16, src);                      \
    }                                                                            \
    CPCOMMIT();                                                                  \
} while (0)

    // prologue: K(0) async, Q tiles plain
    KISSUE(0, 0);
#pragma unroll
    for (int i = 0; i < 4; i++) {
        int w = t + 256 * i;
        int tile = w >> 9, inner = w & 511;
        int row = inner >> 3, sg = inner & 7;
        const bf16* src = (tile ? ql : qh) + (long)row * 1024 + sg * 8;
        *(uint4*)(sm + (tile ? FQ_L : FQ_H) + row * 144 + sg * 16) = *(const uint4*)src;
    }
    __syncthreads();

    // hoist Q fragments (16 q-rows per warp): 4 k4 x 4 regs, hi + lo
    uint32_t qfh[4][4], qfl[4][4];
#pragma unroll
    for (int k4 = 0; k4 < 4; k4++) {
        ldsmA(qfh[k4], sb + FQ_H, wm * 16, k4 * 16, 144, lane);
        ldsmA(qfl[k4], sb + FQ_L, wm * 16, k4 * 16, 144, lane);
    }

    // ---------------- pass A: rowsum only ----------------
    float rs[2] = {0.f, 0.f};
    for (int kt = 0; kt < 32; kt++) {
        CPWAIT(0);
        __syncthreads();
        if (kt + 1 < 32) KISSUE(kt + 1, (kt + 1) & 1);

        uint32_t kb = sb + FKBUF(kt & 1);
        float acc[4][4] = {};
#pragma unroll
        for (int k4 = 0; k4 < 4; k4++) {
            uint32_t bhf[2][4], blf[2][4];
#pragma unroll
            for (int p = 0; p < 2; p++) {
                ldsmB(bhf[p], kb,        wn * 32 + p * 16, k4 * 16, 144, lane);
                ldsmB(blf[p], kb + 9216, wn * 32 + p * 16, k4 * 16, 144, lane);
            }
#pragma unroll
            for (int p = 0; p < 2; p++) {
                mma3(acc[p * 2],     qfh[k4], qfl[k4], &bhf[p][0], &blf[p][0]);
                mma3(acc[p * 2 + 1], qfh[k4], qfl[k4], &bhf[p][2], &blf[p][2]);
            }
        }
#pragma unroll
        for (int j = 0; j < 4; j++) {
            int cl = kt * 64 + wn * 32 + j * 8 + 2 * (lane & 3);
            float m0v = (1.0f - mrow[cl]) * (-1e9f);
            float m1v = (1.0f - mrow[cl + 1]) * (-1e9f);
            rs[0] += __expf(acc[j][0] + m0v) + __expf(acc[j][1] + m1v);
            rs[1] += __expf(acc[j][2] + m0v) + __expf(acc[j][3] + m1v);
        }
    }

    // prefetch K(0) + V(0) for pass B (overlaps reduction)
    KISSUE(0, 0);
    VISSUE(0, 0);

    // reduce rowsum -> invs[64]
#pragma unroll
    for (int i = 0; i < 2; i++) {
        rs[i] += __shfl_xor_sync(0xffffffffu, rs[i], 1);
        rs[i] += __shfl_xor_sync(0xffffffffu, rs[i], 2);
    }
    __syncthreads();
    if ((lane & 3) == 0) {
        part[wn * 64 + wm * 16 + (lane >> 2)]     = rs[0];
        part[wn * 64 + wm * 16 + 8 + (lane >> 2)] = rs[1];
    }
    __syncthreads();
    if (t < 64) invs[t] = 1.0f / (part[t] + part[64 + t]);
    __syncthreads();

    float invr[2];
    invr[0] = invs[wm * 16 + (lane >> 2)];
    invr[1] = invs[wm * 16 + 8 + (lane >> 2)];

    // ---------------- pass B: ONE sync per tile, P in registers ----------------
    float oacc[8][4] = {};
    int r0 = wm * 16 + (lane >> 2);
    for (int kt = 0; kt < 32; kt++) {
        CPWAIT(0);
        __syncthreads();                   // K(kt)+V(kt) visible; prior reads done
        if (kt + 1 < 32) { VISSUE(kt + 1, (kt + 1) & 1); KISSUE(kt + 1, (kt + 1) & 1); }

        uint32_t kb = sb + FKBUF(kt & 1);
        float acc[4][4] = {};
#pragma unroll
        for (int k4 = 0; k4 < 4; k4++) {
            uint32_t bhf[2][4], blf[2][4];
#pragma unroll
            for (int p = 0; p < 2; p++) {
                ldsmB(bhf[p], kb,        wn * 32 + p * 16, k4 * 16, 144, lane);
                ldsmB(blf[p], kb + 9216, wn * 32 + p * 16, k4 * 16, 144, lane);
            }
#pragma unroll
            for (int p = 0; p < 2; p++) {
                mma3(acc[p * 2],     qfh[k4], qfl[k4], &bhf[p][0], &blf[p][0]);
                mma3(acc[p * 2 + 1], qfh[k4], qfl[k4], &bhf[p][2], &blf[p][2]);
            }
        }

        // epilogue: normalize, write attn (fp32), build PV A-frags in regs
        uint32_t pa[2][4];
#pragma unroll
        for (int j = 0; j < 4; j++) {
            int cl = wn * 32 + j * 8 + 2 * (lane & 3);
            int gc = kt * 64 + cl;
            float m0v = (1.0f - mrow[gc]) * (-1e9f);
            float m1v = (1.0f - mrow[gc + 1]) * (-1e9f);
            float e0 = __expf(acc[j][0] + m0v) * invr[0];
            float e1 = __expf(acc[j][1] + m1v) * invr[0];
            float e2 = __expf(acc[j][2] + m0v) * invr[1];
            float e3 = __expf(acc[j][3] + m1v) * invr[1];
            *(float2*)(Abh + (long)r0 * 2048 + gc)       = make_float2(e0, e1);
            *(float2*)(Abh + (long)(r0 + 8) * 2048 + gc) = make_float2(e2, e3);
            int s = j >> 1, o = (j & 1) * 2;
            pa[s][o]     = pack_h2(e0, e1);
            pa[s][o + 1] = pack_h2(e2, e3);
        }

        // PV: O_partial += P(fp16, regs) · (Vh + Vl)^T   — no barrier needed
        uint32_t vb = sb + FVBUF(kt & 1);
#pragma unroll
        for (int s = 0; s < 2; s++)
#pragma unroll
            for (int dt = 0; dt < 4; dt++) {
                uint32_t vh[4], vl[4];
                ldsmB(vh, vb,        dt * 16, wn * 32 + s * 16, 144, lane);
                ldsmB(vl, vb + 9216, dt * 16, wn * 32 + s * 16, 144, lane);
                mma16816h(oacc[dt * 2],     pa[s], &vh[0]);
                mma16816h(oacc[dt * 2],     pa[s], &vl[0]);
                mma16816h(oacc[dt * 2 + 1], pa[s], &vh[2]);
                mma16816h(oacc[dt * 2 + 1], pa[s], &vl[2]);
            }
    }

    // reduce O partials across the 2 wn groups via smem (stride 68 to avoid conflicts)
    __syncthreads();
    float* ored = (float*)sm;            // 2*64*68*4 = 34816 B, reuses Q/K-buf0 area
#pragma unroll
    for (int nt = 0; nt < 8; nt++) {
        int d = nt * 8 + 2 * (lane & 3);
        ored[(wn * 64 + r0) * 68 + d]         = oacc[nt][0];
        ored[(wn * 64 + r0) * 68 + d + 1]     = oacc[nt][1];
        ored[(wn * 64 + r0 + 8) * 68 + d]     = oacc[nt][2];
        ored[(wn * 64 + r0 + 8) * 68 + d + 1] = oacc[nt][3];
    }
    __syncthreads();
    {
        int q = t >> 2, db = (t & 3) * 16;
        long gr = ((long)b * 2048 + qt * 64 + q) * 1024 + h * 64;
#pragma unroll
        for (int j = 0; j < 8; j++) {
            int d = db + j * 2;
            float s0 = ored[q * 68 + d]     + ored[(64 + q) * 68 + d];
            float s1 = ored[q * 68 + d + 1] + ored[(64 + q) * 68 + d + 1];
            store_split2(Bh, Bl, gr + d, s0, s1);
        }
    }
}

// ===========================================================================
extern "C" void kernel_launch(void* const* d_in, const int* in_sizes, int n_in,
                              void* d_out, int out_size) {
    (void)in_sizes; (void)n_in;
    const float* query        = (const float*)d_in[0];
    const float* input_embeds = (const float*)d_in[1];
    const float* mask         = (const float*)d_in[2];
    const float* wq_w = (const float*)d_in[3];
    const float* wq_b = (const float*)d_in[4];
    const float* wk_w = (const float*)d_in[5];
    const float* wk_b = (const float*)d_in[6];
    const float* wv_w = (const float*)d_in[7];
    const float* wv_b = (const float*)d_in[8];
    const float* wo_w = (const float*)d_in[9];
    const float* wo_b = (const float*)d_in[10];
    float* out = (float*)d_out;

    bf16 *qh, *ql, *xh, *xl, *wqh, *wql, *wkh, *wkl, *wvh, *wvl, *woh, *wol;
    bf16 *Qh, *Ql, *Kh, *Kl, *Vh, *Vl, *Bh, *Bl;
    __half *Vth16, *Vtl16;
    float *attn_scratch;
    cudaGetSymbolAddress((void**)&qh, g_qh);   cudaGetSymbolAddress((void**)&ql, g_ql);
    cudaGetSymbolAddress((void**)&xh, g_xh);   cudaGetSymbolAddress((void**)&xl, g_xl);
    cudaGetSymbolAddress((void**)&wqh, g_wqh); cudaGetSymbolAddress((void**)&wql, g_wql);
    cudaGetSymbolAddress((void**)&wkh, g_wkh); cudaGetSymbolAddress((void**)&wkl, g_wkl);
    cudaGetSymbolAddress((void**)&wvh, g_wvh); cudaGetSymbolAddress((void**)&wvl, g_wvl);
    cudaGetSymbolAddress((void**)&woh, g_woh); cudaGetSymbolAddress((void**)&wol, g_wol);
    cudaGetSymbolAddress((void**)&Qh, g_Qh);   cudaGetSymbolAddress((void**)&Ql, g_Ql);
    cudaGetSymbolAddress((void**)&Kh, g_Kh);   cudaGetSymbolAddress((void**)&Kl, g_Kl);
    cudaGetSymbolAddress((void**)&Vh, g_Vh);   cudaGetSymbolAddress((void**)&Vl, g_Vl);
    cudaGetSymbolAddress((void**)&Vth16, g_Vth16);
    cudaGetSymbolAddress((void**)&Vtl16, g_Vtl16);
    cudaGetSymbolAddress((void**)&Bh, g_Bh);   cudaGetSymbolAddress((void**)&Bl, g_Bl);
    cudaGetSymbolAddress((void**)&attn_scratch, g_attn);

    const long OUT_E = 4194304L, ATTN_E = 134217728L;
    float* attn = ((long)out_size >= OUT_E + ATTN_E) ? (out + OUT_E) : attn_scratch;

    const int SM_GEMM = 81920;
    cudaFuncSetAttribute(proj3,      cudaFuncAttributeMaxDynamicSharedMemorySize, SM_GEMM);
    cudaFuncSetAttribute(hgemm_out,  cudaFuncAttributeMaxDynamicSharedMemorySize, SM_GEMM);
    cudaFuncSetAttribute(fused_attn, cudaFuncAttributeMaxDynamicSharedMemorySize, SM_FUSED);

    cvt_all<<<12288, 256>>>(query, input_embeds, wq_w, wk_w, wv_w, wo_w,
                            qh, ql, xh, xl, wqh, wql, wkh, wkl, wvh, wvl, woh, wol);

    proj3<<<dim3(8, 32, 3), 256, SM_GEMM>>>(qh, ql, xh, xl,
                                            wqh, wql, wkh, wkl, wvh, wvl,
                                            wq_b, wk_b, wv_b,
                                            Qh, Ql, Kh, Kl, Vh, Vl);

    vtrans<<<dim3(32, 32), 256>>>(Vh, Vl, Vth16, Vtl16);

    fused_attn<<<dim3(32, 32), 256, SM_FUSED>>>(Qh, Ql, Kh, Kl, Vth16, Vtl16, mask,
                                                attn, Bh, Bl);

    hgemm_out<<<dim3(8, 32), 256, SM_GEMM>>>(Bh, Bl, woh, wol, wo_b, out);
}

// round 14
// speedup vs baseline: 1.0948x; 1.0948x over previous
#include <cuda_runtime.h>
#include <cuda_bf16.h>
#include <cuda_fp16.h>
#include <cstdint>

typedef __nv_bfloat16 bf16;

// ---------------------------------------------------------------------------
static __device__ __forceinline__ uint32_t smem_u32(const void* p) {
    uint32_t a;
    asm("{ .reg .u64 t; cvta.to.shared.u64 t, %1; cvt.u32.u64 %0, t; }" : "=r"(a) : "l"(p));
    return a;
}
static __device__ __forceinline__ void mma16816(float* c, const uint32_t* a, const uint32_t* b) {
    asm volatile("mma.sync.aligned.m16n8k16.row.col.f32.bf16.bf16.f32 "
        "{%0,%1,%2,%3}, {%4,%5,%6,%7}, {%8,%9}, {%0,%1,%2,%3};"
        : "+f"(c[0]), "+f"(c[1]), "+f"(c[2]), "+f"(c[3])
        : "r"(a[0]), "r"(a[1]), "r"(a[2]), "r"(a[3]), "r"(b[0]), "r"(b[1]));
}
static __device__ __forceinline__ void mma16816h(float* c, const uint32_t* a, const uint32_t* b) {
    asm volatile("mma.sync.aligned.m16n8k16.row.col.f32.f16.f16.f32 "
        "{%0,%1,%2,%3}, {%4,%5,%6,%7}, {%8,%9}, {%0,%1,%2,%3};"
        : "+f"(c[0]), "+f"(c[1]), "+f"(c[2]), "+f"(c[3])
        : "r"(a[0]), "r"(a[1]), "r"(a[2]), "r"(a[3]), "r"(b[0]), "r"(b[1]));
}
static __device__ __forceinline__ void mma3(float* c, const uint32_t* ah, const uint32_t* al,
                                            const uint32_t* bh, const uint32_t* bl) {
    mma16816(c, ah, bh); mma16816(c, ah, bl); mma16816(c, al, bh);
}
static __device__ __forceinline__ void ldsm4(uint32_t* r, uint32_t a) {
    asm volatile("ldmatrix.sync.aligned.m8n8.x4.shared.b16 {%0,%1,%2,%3}, [%4];"
        : "=r"(r[0]), "=r"(r[1]), "=r"(r[2]), "=r"(r[3]) : "r"(a));
}
static __device__ __forceinline__ void ldsmA(uint32_t* r, uint32_t base, int m0, int k0, int sbytes, int lane) {
    ldsm4(r, base + (uint32_t)((m0 + (lane & 7) + ((lane >> 3) & 1) * 8) * sbytes
                               + (k0 + ((lane >> 4) << 3)) * 2));
}
static __device__ __forceinline__ void ldsmB(uint32_t* r, uint32_t base, int n0, int k0, int sbytes, int lane) {
    ldsm4(r, base + (uint32_t)((n0 + (lane & 7) + ((lane >> 4) << 3)) * sbytes
                               + (k0 + (((lane >> 3) & 1) << 3)) * 2));
}
#define CP16(sm_, gp_) asm volatile("cp.async.cg.shared.global [%0], [%1], 16;" :: "r"(sm_), "l"(gp_))
#define CPCOMMIT()     asm volatile("cp.async.commit_group;")
#define CPWAIT(n)      asm volatile("cp.async.wait_group %0;" :: "n"(n))

static __device__ __forceinline__ void store_split2(bf16* Ch, bf16* Cl, long off, float x, float y) {
    __align__(4) bf16 h[2] = {__float2bfloat16(x), __float2bfloat16(y)};
    __align__(4) bf16 l[2] = {__float2bfloat16(x - __bfloat162float(h[0])),
                              __float2bfloat16(y - __bfloat162float(h[1]))};
    *(uint32_t*)(Ch + off) = *(uint32_t*)h;
    *(uint32_t*)(Cl + off) = *(uint32_t*)l;
}
static __device__ __forceinline__ void smem_h2f16(char* p, float x, float y) {
    __half2 h = __floats2half2_rn(x, y);
    *(uint32_t*)p = *(uint32_t*)&h;
}

// ---------------- scratch ----------------
__device__ bf16 g_qh[4194304], g_ql[4194304];
__device__ bf16 g_xh[4194304], g_xl[4194304];
__device__ bf16 g_wqh[1048576], g_wql[1048576];
__device__ bf16 g_wkh[1048576], g_wkl[1048576];
__device__ bf16 g_wvh[1048576], g_wvl[1048576];
__device__ bf16 g_woh[1048576], g_wol[1048576];
__device__ bf16 g_Qh[4194304], g_Ql[4194304];
__device__ bf16 g_Kh[4194304], g_Kl[4194304];
__device__ bf16 g_Vh[4194304], g_Vl[4194304];
__device__ __half g_Vth16[4194304];              // V^T fp16 (single): [bh][64 d][2048 tok]
__device__ bf16 g_Bh[4194304], g_Bl[4194304];
__device__ float g_attn[134217728];

// ---------------- merged fp32 -> bf16 hi/lo for all 6 tensors ----------------
__global__ __launch_bounds__(256) void cvt_all(
    const float* __restrict__ s0, const float* __restrict__ s1,
    const float* __restrict__ s2, const float* __restrict__ s3,
    const float* __restrict__ s4, const float* __restrict__ s5,
    bf16* __restrict__ h0, bf16* __restrict__ l0, bf16* __restrict__ h1, bf16* __restrict__ l1,
    bf16* __restrict__ h2, bf16* __restrict__ l2, bf16* __restrict__ h3, bf16* __restrict__ l3,
    bf16* __restrict__ h4, bf16* __restrict__ l4, bf16* __restrict__ h5, bf16* __restrict__ l5)
{
    long i = (long)blockIdx.x * 256 + threadIdx.x;   // < 3145728
    const float* src; bf16 *h, *l; long li;
    if (i < 1048576)      { src = s0; h = h0; l = l0; li = i; }
    else if (i < 2097152) { src = s1; h = h1; l = l1; li = i - 1048576; }
    else {
        long j = i - 2097152;
        int w = (int)(j >> 18);
        li = j & 262143;
        src = (w == 0) ? s2 : (w == 1) ? s3 : (w == 2) ? s4 : s5;
        h   = (w == 0) ? h2 : (w == 1) ? h3 : (w == 2) ? h4 : h5;
        l   = (w == 0) ? l2 : (w == 1) ? l3 : (w == 2) ? l4 : l5;
    }
    float4 v = ((const float4*)src)[li];
    float f[4] = {v.x, v.y, v.z, v.w};
    __align__(8) bf16 hv[4], lv[4];
#pragma unroll
    for (int j = 0; j < 4; j++) {
        hv[j] = __float2bfloat16(f[j]);
        lv[j] = __float2bfloat16(f[j] - __bfloat162float(hv[j]));
    }
    ((uint2*)h)[li] = *(uint2*)hv;
    ((uint2*)l)[li] = *(uint2*)lv;
}

// ---------------------------------------------------------------------------
// hgemm body (proven): 256 threads, 4m x 2n, 128x128, BK=32, double-buffered
// ---------------------------------------------------------------------------
static __device__ __forceinline__ void hgemm_body(
    const bf16* __restrict__ Ah, const bf16* __restrict__ Al,
    const bf16* __restrict__ Bh, const bf16* __restrict__ Bl,
    const float* __restrict__ bias, float* __restrict__ Cf,
    bf16* __restrict__ Ch, bf16* __restrict__ Cl,
    int K, int lda, int ldb, int ldc, char* sm)
{
    uint32_t sb = smem_u32(sm);
    int t = threadIdx.x, lane = t & 31, wid = t >> 5;
    int wm = wid & 3, wn = wid >> 2;
    long m0 = blockIdx.y * 128, n0 = blockIdx.x * 128;

    const bf16* g0 = Ah + m0 * lda;
    const bf16* g1 = Al + m0 * lda;
    const bf16* g2 = Bh + n0 * ldb;
    const bf16* g3 = Bl + n0 * ldb;

#define G_ISSUE(c_, buf_) do {                                                  \
    int _c = (c_); uint32_t _bs = sb + (buf_) * 40960;                          \
    _Pragma("unroll")                                                           \
    for (int i = 0; i < 8; i++) {                                               \
        const int tile = i >> 1;                                                \
        int w = t + 256 * (i & 1);                                               \
        int row = w >> 2, sg = w & 3;                                           \
        const bf16* gp = (tile == 0 ? g0 : tile == 1 ? g1 : tile == 2 ? g2 : g3)\
            + (long)row * (tile < 2 ? lda : ldb) + _c * 32 + sg * 8;            \
        CP16(_bs + tile * 10240 + row * 80 + sg * 16, gp);                      \
    }                                                                           \
    CPCOMMIT();                                                                 \
} while (0)

    float acc[2][8][4] = {};
    int nc = K >> 5;
    G_ISSUE(0, 0);
    G_ISSUE(1, 1);
    for (int c = 0; c < nc; c++) {
        if (c + 1 < nc) { CPWAIT(1); } else { CPWAIT(0); }
        __syncthreads();
        uint32_t bAh = sb + (c & 1) * 40960, bAl = bAh + 10240;
        uint32_t bBh = bAh + 20480, bBl = bAh + 30720;
#pragma unroll
        for (int k0 = 0; k0 < 32; k0 += 16) {
            uint32_t ah[2][4], al[2][4], bhf[4][4], blf[4][4];
#pragma unroll
            for (int mt = 0; mt < 2; mt++) {
                ldsmA(ah[mt], bAh, wm * 32 + mt * 16, k0, 80, lane);
                ldsmA(al[mt], bAl, wm * 32 + mt * 16, k0, 80, lane);
            }
#pragma unroll
            for (int p = 0; p < 4; p++) {
                ldsmB(bhf[p], bBh, wn * 64 + p * 16, k0, 80, lane);
                ldsmB(blf[p], bBl, wn * 64 + p * 16, k0, 80, lane);
            }
#pragma unroll
            for (int mt = 0; mt < 2; mt++)
#pragma unroll
                for (int p = 0; p < 4; p++) {
                    mma3(acc[mt][p * 2],     ah[mt], al[mt], &bhf[p][0], &blf[p][0]);
                    mma3(acc[mt][p * 2 + 1], ah[mt], al[mt], &bhf[p][2], &blf[p][2]);
                }
        }
        __syncthreads();
        if (c + 2 < nc) G_ISSUE(c + 2, c & 1);
    }
#undef G_ISSUE

#pragma unroll
    for (int mt = 0; mt < 2; mt++)
#pragma unroll
        for (int nt = 0; nt < 8; nt++) {
            float* cc = acc[mt][nt];
            long r0 = m0 + wm * 32 + mt * 16 + (lane >> 2);
            int col = (int)n0 + wn * 64 + nt * 8 + 2 * (lane & 3);
            float b0 = bias[col], b1 = bias[col + 1];
            float f0 = cc[0] + b0, f1 = cc[1] + b1, f2 = cc[2] + b0, f3 = cc[3] + b1;
            if (Cf) {
                *(float2*)(Cf + r0 * ldc + col) = make_float2(f0, f1);
                *(float2*)(Cf + (r0 + 8) * ldc + col) = make_float2(f2, f3);
            }
            if (Ch) {
                store_split2(Ch, Cl, r0 * ldc + col, f0, f1);
                store_split2(Ch, Cl, (r0 + 8) * ldc + col, f2, f3);
            }
        }
}

__global__ __launch_bounds__(256) void proj3(
    const bf16* __restrict__ qh, const bf16* __restrict__ ql,
    const bf16* __restrict__ xh, const bf16* __restrict__ xl,
    const bf16* __restrict__ wqh, const bf16* __restrict__ wql,
    const bf16* __restrict__ wkh, const bf16* __restrict__ wkl,
    const bf16* __restrict__ wvh, const bf16* __restrict__ wvl,
    const float* __restrict__ bq, const float* __restrict__ bk, const float* __restrict__ bv,
    bf16* __restrict__ Qh, bf16* __restrict__ Ql,
    bf16* __restrict__ Kh, bf16* __restrict__ Kl,
    bf16* __restrict__ Vh, bf16* __restrict__ Vl)
{
    extern __shared__ char sm[];
    int z = blockIdx.z;
    const bf16* Ah = (z == 0) ? qh : xh;
    const bf16* Al = (z == 0) ? ql : xl;
    const bf16* Bh = (z == 0) ? wqh : (z == 1) ? wkh : wvh;
    const bf16* Bl = (z == 0) ? wql : (z == 1) ? wkl : wvl;
    const float* bias = (z == 0) ? bq : (z == 1) ? bk : bv;
    bf16* Ch = (z == 0) ? Qh : (z == 1) ? Kh : Vh;
    bf16* Cl = (z == 0) ? Ql : (z == 1) ? Kl : Vl;
    hgemm_body(Ah, Al, Bh, Bl, bias, nullptr, Ch, Cl, 1024, 1024, 1024, 1024, sm);
}

__global__ __launch_bounds__(256) void hgemm_out(
    const bf16* __restrict__ Ah, const bf16* __restrict__ Al,
    const bf16* __restrict__ Bh, const bf16* __restrict__ Bl,
    const float* __restrict__ bias, float* __restrict__ Cf)
{
    extern __shared__ char sm[];
    hgemm_body(Ah, Al, Bh, Bl, bias, Cf, nullptr, nullptr, 1024, 1024, 1024, 1024, sm);
}

// ---------------------------------------------------------------------------
// vtrans: V bf16 hi+lo -> per (b,h) [64 d][2048 tok], fp16 single (rn of sum)
// ---------------------------------------------------------------------------
__global__ __launch_bounds__(256) void vtrans(
    const bf16* __restrict__ Vh, const bf16* __restrict__ Vl,
    __half* __restrict__ Th) {
    __shared__ bf16 sh[64][72], sl[64][72];
    int t = threadIdx.x, tt = blockIdx.x, bh = blockIdx.y;
    int b = bh >> 4, h = bh & 15;
    const bf16* srch = Vh + ((long)b * 2048 + tt * 64) * 1024 + h * 64;
    const bf16* srcl = Vl + ((long)b * 2048 + tt * 64) * 1024 + h * 64;
#pragma unroll
    for (int i = 0; i < 2; i++) {
        int s = t + 256 * i, row = s >> 3, seg = s & 7;
        *(uint4*)&sh[row][seg * 8] = *(const uint4*)(srch + (long)row * 1024 + seg * 8);
        *(uint4*)&sl[row][seg * 8] = *(const uint4*)(srcl + (long)row * 1024 + seg * 8);
    }
    __syncthreads();
    __half* dh = Th + (long)bh * 64 * 2048 + tt * 64;
#pragma unroll
    for (int i = 0; i < 2; i++) {
        int s = t + 256 * i, d = s >> 3, seg = s & 7;
        __align__(16) __half th[8];
#pragma unroll
        for (int j = 0; j < 8; j++) {
            float f = __bfloat162float(sh[seg * 8 + j][d]) + __bfloat162float(sl[seg * 8 + j][d]);
            th[j] = __float2half_rn(f);
        }
        *(uint4*)(dh + (long)d * 2048 + seg * 8) = *(uint4*)th;
    }
}

// ---------------------------------------------------------------------------
// fused_attn (round-12 structure, V single fp16):
// 256 threads, 64-q tile, 64-wide K tiles, 2 CTAs/SM, Q frags hoisted.
// QK: bf16 3-product. PV: P fp16 x V fp16 (single product).
// smem (bytes), tiles stride 144:
//   Q hi @0, Q lo @9216
//   K buf0 @18432 (hi,lo), buf1 @36864
//   P fp16 @55296 (9216) | V fp16 @64512 (9216)
//   part @73728 (256 f), invs @74752 (64 f) -> total 75008 -> 2 CTAs/SM
// ---------------------------------------------------------------------------
#define FQ_H  0
#define FQ_L  9216
#define FKBUF(b) (18432 + (b) * 18432)
#define FP_H  55296
#define FV_H  64512
#define FPART 73728
#define FINVS 74752
#define SM_FUSED 75008

__global__ __launch_bounds__(256, 2) void fused_attn(
    const bf16* __restrict__ Qh, const bf16* __restrict__ Ql,
    const bf16* __restrict__ Kh, const bf16* __restrict__ Kl,
    const __half* __restrict__ Vth,
    const float* __restrict__ mask,
    float* __restrict__ A, bf16* __restrict__ Bh, bf16* __restrict__ Bl)
{
    extern __shared__ char sm[];
    uint32_t sb = smem_u32(sm);
    int t = threadIdx.x, lane = t & 31, wid = t >> 5;
    int wm = wid & 1, wn = wid >> 1;          // 2m x 4n; warp tile 32q x 16k
    int qt = blockIdx.x, bh = blockIdx.y;
    int b = bh >> 4, h = bh & 15;

    const bf16* qh = Qh + ((long)b * 2048 + qt * 64) * 1024 + h * 64;
    const bf16* ql = Ql + ((long)b * 2048 + qt * 64) * 1024 + h * 64;
    const bf16* kh = Kh + (long)b * 2048 * 1024 + h * 64;
    const bf16* kl = Kl + (long)b * 2048 * 1024 + h * 64;
    const __half* vth = Vth + (long)bh * 64 * 2048;
    float* Abh = A + ((long)bh * 2048 + qt * 64) * 2048;
    const float* mrow = mask + (long)b * 2048;

    float* part = (float*)(sm + FPART);
    float* invs = (float*)(sm + FINVS);

#define KISSUE(kt_, buf_) do {                                                   \
    int _kt = (kt_); uint32_t _kb = sb + FKBUF(buf_);                            \
    _Pragma("unroll")                                                            \
    for (int i = 0; i < 4; i++) {                                                \
        int w = t + 256 * i;                                                     \
        int tile = w >> 9, inner = w & 511;                                      \
        int row = inner >> 3, sg = inner & 7;                                    \
        const bf16* src = (tile ? kl : kh) + (long)(_kt * 64 + row) * 1024 + sg * 8; \
        CP16(_kb + tile * 9216 + row * 144 + sg * 16, src);                      \
    }                                                                            \
    CPCOMMIT();                                                                  \
} while (0)

// V fp16 tile kt (64 d-rows x 64 k): 512 segs, 2 per thread
#define VISSUE(kt_) do {                                                         \
    int _kt = (kt_);                                                             \
    _Pragma("unroll")                                                            \
    for (int i = 0; i < 2; i++) {                                                \
        int w = t + 256 * i;                                                     \
        int row = w >> 3, sg = w & 7;                                            \
        const __half* src = vth + (long)row * 2048 + _kt * 64 + sg * 8;          \
        CP16(sb + FV_H + row * 144 + sg * 16, src);                              \
    }                                                                            \
    CPCOMMIT();                                                                  \
} while (0)

    // prologue: K(0) async, Q tiles plain
    KISSUE(0, 0);
#pragma unroll
    for (int i = 0; i < 4; i++) {
        int w = t + 256 * i;
        int tile = w >> 9, inner = w & 511;
        int row = inner >> 3, sg = inner & 7;
        const bf16* src = (tile ? ql : qh) + (long)row * 1024 + sg * 8;
        *(uint4*)(sm + (tile ? FQ_L : FQ_H) + row * 144 + sg * 16) = *(const uint4*)src;
    }
    __syncthreads();   // Q visible to all warps

    // hoist Q fragments: 2 mt x 4 k4 x 4 regs, hi + lo
    uint32_t qfh[2][4][4], qfl[2][4][4];
#pragma unroll
    for (int mt = 0; mt < 2; mt++)
#pragma unroll
        for (int k4 = 0; k4 < 4; k4++) {
            ldsmA(qfh[mt][k4], sb + FQ_H, wm * 32 + mt * 16, k4 * 16, 144, lane);
            ldsmA(qfl[mt][k4], sb + FQ_L, wm * 32 + mt * 16, k4 * 16, 144, lane);
        }

    // ---------------- pass A: rowsum only ----------------
    float rs[4] = {0.f, 0.f, 0.f, 0.f};
    for (int kt = 0; kt < 32; kt++) {
        CPWAIT(0);
        __syncthreads();
        if (kt + 1 < 32) KISSUE(kt + 1, (kt + 1) & 1);

        uint32_t kb = sb + FKBUF(kt & 1);
        float acc[2][2][4] = {};
#pragma unroll
        for (int k4 = 0; k4 < 4; k4++) {
            uint32_t bhf[4], blf[4];
            ldsmB(bhf, kb,        wn * 16, k4 * 16, 144, lane);
            ldsmB(blf, kb + 9216, wn * 16, k4 * 16, 144, lane);
#pragma unroll
            for (int mt = 0; mt < 2; mt++) {
                mma3(acc[mt][0], qfh[mt][k4], qfl[mt][k4], &bhf[0], &blf[0]);
                mma3(acc[mt][1], qfh[mt][k4], qfl[mt][k4], &bhf[2], &blf[2]);
            }
        }
#pragma unroll
        for (int nt = 0; nt < 2; nt++) {
            int cl = kt * 64 + wn * 16 + nt * 8 + 2 * (lane & 3);
            float m0v = (1.0f - mrow[cl]) * (-1e9f);
            float m1v = (1.0f - mrow[cl + 1]) * (-1e9f);
#pragma unroll
            for (int mt = 0; mt < 2; mt++) {
                float* cc = acc[mt][nt];
                rs[mt * 2 + 0] += __expf(cc[0] + m0v) + __expf(cc[1] + m1v);
                rs[mt * 2 + 1] += __expf(cc[2] + m0v) + __expf(cc[3] + m1v);
            }
        }
    }

    KISSUE(0, 0);     // K(0) for pass B

    // reduce rowsum -> invs[64]
#pragma unroll
    for (int i = 0; i < 4; i++) {
        rs[i] += __shfl_xor_sync(0xffffffffu, rs[i], 1);
        rs[i] += __shfl_xor_sync(0xffffffffu, rs[i], 2);
    }
    __syncthreads();
    if ((lane & 3) == 0) {
#pragma unroll
        for (int mt = 0; mt < 2; mt++)
#pragma unroll
            for (int hf = 0; hf < 2; hf++)
                part[wn * 64 + wm * 32 + mt * 16 + hf * 8 + (lane >> 2)] = rs[mt * 2 + hf];
    }
    __syncthreads();
    if (t < 64)
        invs[t] = 1.0f / (part[t] + part[64 + t] + part[128 + t] + part[192 + t]);
    __syncthreads();

    float invr[2][2];
#pragma unroll
    for (int mt = 0; mt < 2; mt++) {
        invr[mt][0] = invs[wm * 32 + mt * 16 + (lane >> 2)];
        invr[mt][1] = invs[wm * 32 + mt * 16 + 8 + (lane >> 2)];
    }

    // ---------------- pass B ----------------
    float oacc[2][2][4] = {};
    for (int kt = 0; kt < 32; kt++) {
        CPWAIT(0);
        __syncthreads();                   // K(kt) ready; prior P/V reads done
        VISSUE(kt);                        // V first (released by wait_group 1)
        if (kt + 1 < 32) KISSUE(kt + 1, (kt + 1) & 1);

        uint32_t kb = sb + FKBUF(kt & 1);
        float acc[2][2][4] = {};
#pragma unroll
        for (int k4 = 0; k4 < 4; k4++) {
            uint32_t bhf[4], blf[4];
            ldsmB(bhf, kb,        wn * 16, k4 * 16, 144, lane);
            ldsmB(blf, kb + 9216, wn * 16, k4 * 16, 144, lane);
#pragma unroll
            for (int mt = 0; mt < 2; mt++) {
                mma3(acc[mt][0], qfh[mt][k4], qfl[mt][k4], &bhf[0], &blf[0]);
                mma3(acc[mt][1], qfh[mt][k4], qfl[mt][k4], &bhf[2], &blf[2]);
            }
        }

        // epilogue: normalize, write attn (fp32 exact), pack P fp16 -> smem
#pragma unroll
        for (int nt = 0; nt < 2; nt++) {
            int cl = wn * 16 + nt * 8 + 2 * (lane & 3);
            int gc = kt * 64 + cl;
            float m0v = (1.0f - mrow[gc]) * (-1e9f);
            float m1v = (1.0f - mrow[gc + 1]) * (-1e9f);
#pragma unroll
            for (int mt = 0; mt < 2; mt++) {
                float* cc = acc[mt][nt];
                int r0 = wm * 32 + mt * 16 + (lane >> 2);
                float e0 = __expf(cc[0] + m0v) * invr[mt][0];
                float e1 = __expf(cc[1] + m1v) * invr[mt][0];
                float e2 = __expf(cc[2] + m0v) * invr[mt][1];
                float e3 = __expf(cc[3] + m1v) * invr[mt][1];
                *(float2*)(Abh + (long)r0 * 2048 + gc)       = make_float2(e0, e1);
                *(float2*)(Abh + (long)(r0 + 8) * 2048 + gc) = make_float2(e2, e3);
                smem_h2f16(sm + FP_H + r0 * 144 + cl * 2, e0, e1);
                smem_h2f16(sm + FP_H + (r0 + 8) * 144 + cl * 2, e2, e3);
            }
        }

        if (kt + 1 < 32) { CPWAIT(1); } else { CPWAIT(0); }
        __syncthreads();                   // V(kt) + P visible

        // O += P(fp16) · V(fp16)^T  (single product)
#pragma unroll
        for (int k4 = 0; k4 < 4; k4++) {
            uint32_t ah[2][4], bhf[4];
#pragma unroll
            for (int mt = 0; mt < 2; mt++)
                ldsmA(ah[mt], sb + FP_H, wm * 32 + mt * 16, k4 * 16, 144, lane);
            ldsmB(bhf, sb + FV_H, wn * 16, k4 * 16, 144, lane);
#pragma unroll
            for (int mt = 0; mt < 2; mt++) {
                mma16816h(oacc[mt][0], ah[mt], &bhf[0]);
                mma16816h(oacc[mt][1], ah[mt], &bhf[2]);
            }
        }
    }

    // write blended split [b, q, h*64+d]
#pragma unroll
    for (int mt = 0; mt < 2; mt++)
#pragma unroll
        for (int nt = 0; nt < 2; nt++) {
            float* cc = oacc[mt][nt];
            long r0 = (long)b * 2048 + qt * 64 + wm * 32 + mt * 16 + (lane >> 2);
            int col = h * 64 + wn * 16 + nt * 8 + 2 * (lane & 3);
            store_split2(Bh, Bl, r0 * 1024 + col, cc[0], cc[1]);
            store_split2(Bh, Bl, (r0 + 8) * 1024 + col, cc[2], cc[3]);
        }
}

// ===========================================================================
extern "C" void kernel_launch(void* const* d_in, const int* in_sizes, int n_in,
                              void* d_out, int out_size) {
    (void)in_sizes; (void)n_in;
    const float* query        = (const float*)d_in[0];
    const float* input_embeds = (const float*)d_in[1];
    const float* mask         = (const float*)d_in[2];
    const float* wq_w = (const float*)d_in[3];
    const float* wq_b = (const float*)d_in[4];
    const float* wk_w = (const float*)d_in[5];
    const float* wk_b = (const float*)d_in[6];
    const float* wv_w = (const float*)d_in[7];
    const float* wv_b = (const float*)d_in[8];
    const float* wo_w = (const float*)d_in[9];
    const float* wo_b = (const float*)d_in[10];
    float* out = (float*)d_out;

    bf16 *qh, *ql, *xh, *xl, *wqh, *wql, *wkh, *wkl, *wvh, *wvl, *woh, *wol;
    bf16 *Qh, *Ql, *Kh, *Kl, *Vh, *Vl, *Bh, *Bl;
    __half *Vth16;
    float *attn_scratch;
    cudaGetSymbolAddress((void**)&qh, g_qh);   cudaGetSymbolAddress((void**)&ql, g_ql);
    cudaGetSymbolAddress((void**)&xh, g_xh);   cudaGetSymbolAddress((void**)&xl, g_xl);
    cudaGetSymbolAddress((void**)&wqh, g_wqh); cudaGetSymbolAddress((void**)&wql, g_wql);
    cudaGetSymbolAddress((void**)&wkh, g_wkh); cudaGetSymbolAddress((void**)&wkl, g_wkl);
    cudaGetSymbolAddress((void**)&wvh, g_wvh); cudaGetSymbolAddress((void**)&wvl, g_wvl);
    cudaGetSymbolAddress((void**)&woh, g_woh); cudaGetSymbolAddress((void**)&wol, g_wol);
    cudaGetSymbolAddress((void**)&Qh, g_Qh);   cudaGetSymbolAddress((void**)&Ql, g_Ql);
    cudaGetSymbolAddress((void**)&Kh, g_Kh);   cudaGetSymbolAddress((void**)&Kl, g_Kl);
    cudaGetSymbolAddress((void**)&Vh, g_Vh);   cudaGetSymbolAddress((void**)&Vl, g_Vl);
    cudaGetSymbolAddress((void**)&Vth16, g_Vth16);
    cudaGetSymbolAddress((void**)&Bh, g_Bh);   cudaGetSymbolAddress((void**)&Bl, g_Bl);
    cudaGetSymbolAddress((void**)&attn_scratch, g_attn);

    const long OUT_E = 4194304L, ATTN_E = 134217728L;
    float* attn = ((long)out_size >= OUT_E + ATTN_E) ? (out + OUT_E) : attn_scratch;

    const int SM_GEMM = 81920;
    cudaFuncSetAttribute(proj3,      cudaFuncAttributeMaxDynamicSharedMemorySize, SM_GEMM);
    cudaFuncSetAttribute(hgemm_out,  cudaFuncAttributeMaxDynamicSharedMemorySize, SM_GEMM);
    cudaFuncSetAttribute(fused_attn, cudaFuncAttributeMaxDynamicSharedMemorySize, SM_FUSED);

    cvt_all<<<12288, 256>>>(query, input_embeds, wq_w, wk_w, wv_w, wo_w,
                            qh, ql, xh, xl, wqh, wql, wkh, wkl, wvh, wvl, woh, wol);

    proj3<<<dim3(8, 32, 3), 256, SM_GEMM>>>(qh, ql, xh, xl,
                                            wqh, wql, wkh, wkl, wvh, wvl,
                                            wq_b, wk_b, wv_b,
                                            Qh, Ql, Kh, Kl, Vh, Vl);

    vtrans<<<dim3(32, 32), 256>>>(Vh, Vl, Vth16);

    fused_attn<<<dim3(32, 32), 256, SM_FUSED>>>(Qh, Ql, Kh, Kl, Vth16, mask,
                                                attn, Bh, Bl);

    hgemm_out<<<dim3(8, 32), 256, SM_GEMM>>>(Bh, Bl, woh, wol, wo_b, out);
}

// round 15
// speedup vs baseline: 1.1122x; 1.0159x over previous
#include <cuda_runtime.h>
#include <cuda_bf16.h>
#include <cuda_fp16.h>
#include <cstdint>

typedef __nv_bfloat16 bf16;

// ---------------------------------------------------------------------------
static __device__ __forceinline__ uint32_t smem_u32(const void* p) {
    uint32_t a;
    asm("{ .reg .u64 t; cvta.to.shared.u64 t, %1; cvt.u32.u64 %0, t; }" : "=r"(a) : "l"(p));
    return a;
}
static __device__ __forceinline__ void mma16816(float* c, const uint32_t* a, const uint32_t* b) {
    asm volatile("mma.sync.aligned.m16n8k16.row.col.f32.bf16.bf16.f32 "
        "{%0,%1,%2,%3}, {%4,%5,%6,%7}, {%8,%9}, {%0,%1,%2,%3};"
        : "+f"(c[0]), "+f"(c[1]), "+f"(c[2]), "+f"(c[3])
        : "r"(a[0]), "r"(a[1]), "r"(a[2]), "r"(a[3]), "r"(b[0]), "r"(b[1]));
}
static __device__ __forceinline__ void mma16816h(float* c, const uint32_t* a, const uint32_t* b) {
    asm volatile("mma.sync.aligned.m16n8k16.row.col.f32.f16.f16.f32 "
        "{%0,%1,%2,%3}, {%4,%5,%6,%7}, {%8,%9}, {%0,%1,%2,%3};"
        : "+f"(c[0]), "+f"(c[1]), "+f"(c[2]), "+f"(c[3])
        : "r"(a[0]), "r"(a[1]), "r"(a[2]), "r"(a[3]), "r"(b[0]), "r"(b[1]));
}
static __device__ __forceinline__ void mma3(float* c, const uint32_t* ah, const uint32_t* al,
                                            const uint32_t* bh, const uint32_t* bl) {
    mma16816(c, ah, bh); mma16816(c, ah, bl); mma16816(c, al, bh);
}
static __device__ __forceinline__ void ldsm4(uint32_t* r, uint32_t a) {
    asm volatile("ldmatrix.sync.aligned.m8n8.x4.shared.b16 {%0,%1,%2,%3}, [%4];"
        : "=r"(r[0]), "=r"(r[1]), "=r"(r[2]), "=r"(r[3]) : "r"(a));
}
static __device__ __forceinline__ void ldsmA(uint32_t* r, uint32_t base, int m0, int k0, int sbytes, int lane) {
    ldsm4(r, base + (uint32_t)((m0 + (lane & 7) + ((lane >> 3) & 1) * 8) * sbytes
                               + (k0 + ((lane >> 4) << 3)) * 2));
}
static __device__ __forceinline__ void ldsmB(uint32_t* r, uint32_t base, int n0, int k0, int sbytes, int lane) {
    ldsm4(r, base + (uint32_t)((n0 + (lane & 7) + ((lane >> 4) << 3)) * sbytes
                               + (k0 + (((lane >> 3) & 1) << 3)) * 2));
}
#define CP16(sm_, gp_) asm volatile("cp.async.cg.shared.global [%0], [%1], 16;" :: "r"(sm_), "l"(gp_))
#define CPCOMMIT()     asm volatile("cp.async.commit_group;")
#define CPWAIT(n)      asm volatile("cp.async.wait_group %0;" :: "n"(n))

static __device__ __forceinline__ void store_split2(bf16* Ch, bf16* Cl, long off, float x, float y) {
    __align__(4) bf16 h[2] = {__float2bfloat16(x), __float2bfloat16(y)};
    __align__(4) bf16 l[2] = {__float2bfloat16(x - __bfloat162float(h[0])),
                              __float2bfloat16(y - __bfloat162float(h[1]))};
    *(uint32_t*)(Ch + off) = *(uint32_t*)h;
    *(uint32_t*)(Cl + off) = *(uint32_t*)l;
}
static __device__ __forceinline__ void smem_h2f16(char* p, float x, float y) {
    __half2 h = __floats2half2_rn(x, y);
    *(uint32_t*)p = *(uint32_t*)&h;
}

// ---------------- scratch ----------------
__device__ bf16 g_qh[4194304], g_ql[4194304];
__device__ bf16 g_xh[4194304], g_xl[4194304];
__device__ bf16 g_wqh[1048576], g_wql[1048576];
__device__ bf16 g_wkh[1048576], g_wkl[1048576];
__device__ bf16 g_wvh[1048576], g_wvl[1048576];
__device__ bf16 g_woh[1048576], g_wol[1048576];
__device__ bf16 g_Qh[4194304], g_Ql[4194304];
__device__ bf16 g_Kh[4194304], g_Kl[4194304];
__device__ bf16 g_Vh[4194304], g_Vl[4194304];
__device__ __half g_Vth16[4194304];              // V^T fp16 (single): [bh][64 d][2048 tok]
__device__ bf16 g_Bh[4194304], g_Bl[4194304];
__device__ float g_attn[134217728];

// ---------------- merged fp32 -> bf16 hi/lo for all 6 tensors ----------------
__global__ __launch_bounds__(256) void cvt_all(
    const float* __restrict__ s0, const float* __restrict__ s1,
    const float* __restrict__ s2, const float* __restrict__ s3,
    const float* __restrict__ s4, const float* __restrict__ s5,
    bf16* __restrict__ h0, bf16* __restrict__ l0, bf16* __restrict__ h1, bf16* __restrict__ l1,
    bf16* __restrict__ h2, bf16* __restrict__ l2, bf16* __restrict__ h3, bf16* __restrict__ l3,
    bf16* __restrict__ h4, bf16* __restrict__ l4, bf16* __restrict__ h5, bf16* __restrict__ l5)
{
    long i = (long)blockIdx.x * 256 + threadIdx.x;   // < 3145728
    const float* src; bf16 *h, *l; long li;
    if (i < 1048576)      { src = s0; h = h0; l = l0; li = i; }
    else if (i < 2097152) { src = s1; h = h1; l = l1; li = i - 1048576; }
    else {
        long j = i - 2097152;
        int w = (int)(j >> 18);
        li = j & 262143;
        src = (w == 0) ? s2 : (w == 1) ? s3 : (w == 2) ? s4 : s5;
        h   = (w == 0) ? h2 : (w == 1) ? h3 : (w == 2) ? h4 : h5;
        l   = (w == 0) ? l2 : (w == 1) ? l3 : (w == 2) ? l4 : l5;
    }
    float4 v = ((const float4*)src)[li];
    float f[4] = {v.x, v.y, v.z, v.w};
    __align__(8) bf16 hv[4], lv[4];
#pragma unroll
    for (int j = 0; j < 4; j++) {
        hv[j] = __float2bfloat16(f[j]);
        lv[j] = __float2bfloat16(f[j] - __bfloat162float(hv[j]));
    }
    ((uint2*)h)[li] = *(uint2*)hv;
    ((uint2*)l)[li] = *(uint2*)lv;
}

// ---------------------------------------------------------------------------
// hgemm body (proven): 256 threads, 4m x 2n, 128x128, BK=32, double-buffered
// ---------------------------------------------------------------------------
static __device__ __forceinline__ void hgemm_body(
    const bf16* __restrict__ Ah, const bf16* __restrict__ Al,
    const bf16* __restrict__ Bh, const bf16* __restrict__ Bl,
    const float* __restrict__ bias, float* __restrict__ Cf,
    bf16* __restrict__ Ch, bf16* __restrict__ Cl,
    int K, int lda, int ldb, int ldc, char* sm)
{
    uint32_t sb = smem_u32(sm);
    int t = threadIdx.x, lane = t & 31, wid = t >> 5;
    int wm = wid & 3, wn = wid >> 2;
    long m0 = blockIdx.y * 128, n0 = blockIdx.x * 128;

    const bf16* g0 = Ah + m0 * lda;
    const bf16* g1 = Al + m0 * lda;
    const bf16* g2 = Bh + n0 * ldb;
    const bf16* g3 = Bl + n0 * ldb;

#define G_ISSUE(c_, buf_) do {                                                  \
    int _c = (c_); uint32_t _bs = sb + (buf_) * 40960;                          \
    _Pragma("unroll")                                                           \
    for (int i = 0; i < 8; i++) {                                               \
        const int tile = i >> 1;                                                \
        int w = t + 256 * (i & 1);                                               \
        int row = w >> 2, sg = w & 3;                                           \
        const bf16* gp = (tile == 0 ? g0 : tile == 1 ? g1 : tile == 2 ? g2 : g3)\
            + (long)row * (tile < 2 ? lda : ldb) + _c * 32 + sg * 8;            \
        CP16(_bs + tile * 10240 + row * 80 + sg * 16, gp);                      \
    }                                                                           \
    CPCOMMIT();                                                                 \
} while (0)

    float acc[2][8][4] = {};
    int nc = K >> 5;
    G_ISSUE(0, 0);
    G_ISSUE(1, 1);
    for (int c = 0; c < nc; c++) {
        if (c + 1 < nc) { CPWAIT(1); } else { CPWAIT(0); }
        __syncthreads();
        uint32_t bAh = sb + (c & 1) * 40960, bAl = bAh + 10240;
        uint32_t bBh = bAh + 20480, bBl = bAh + 30720;
#pragma unroll
        for (int k0 = 0; k0 < 32; k0 += 16) {
            uint32_t ah[2][4], al[2][4], bhf[4][4], blf[4][4];
#pragma unroll
            for (int mt = 0; mt < 2; mt++) {
                ldsmA(ah[mt], bAh, wm * 32 + mt * 16, k0, 80, lane);
                ldsmA(al[mt], bAl, wm * 32 + mt * 16, k0, 80, lane);
            }
#pragma unroll
            for (int p = 0; p < 4; p++) {
                ldsmB(bhf[p], bBh, wn * 64 + p * 16, k0, 80, lane);
                ldsmB(blf[p], bBl, wn * 64 + p * 16, k0, 80, lane);
            }
#pragma unroll
            for (int mt = 0; mt < 2; mt++)
#pragma unroll
                for (int p = 0; p < 4; p++) {
                    mma3(acc[mt][p * 2],     ah[mt], al[mt], &bhf[p][0], &blf[p][0]);
                    mma3(acc[mt][p * 2 + 1], ah[mt], al[mt], &bhf[p][2], &blf[p][2]);
                }
        }
        __syncthreads();
        if (c + 2 < nc) G_ISSUE(c + 2, c & 1);
    }
#undef G_ISSUE

#pragma unroll
    for (int mt = 0; mt < 2; mt++)
#pragma unroll
        for (int nt = 0; nt < 8; nt++) {
            float* cc = acc[mt][nt];
            long r0 = m0 + wm * 32 + mt * 16 + (lane >> 2);
            int col = (int)n0 + wn * 64 + nt * 8 + 2 * (lane & 3);
            float b0 = bias[col], b1 = bias[col + 1];
            float f0 = cc[0] + b0, f1 = cc[1] + b1, f2 = cc[2] + b0, f3 = cc[3] + b1;
            if (Cf) {
                *(float2*)(Cf + r0 * ldc + col) = make_float2(f0, f1);
                *(float2*)(Cf + (r0 + 8) * ldc + col) = make_float2(f2, f3);
            }
            if (Ch) {
                store_split2(Ch, Cl, r0 * ldc + col, f0, f1);
                store_split2(Ch, Cl, (r0 + 8) * ldc + col, f2, f3);
            }
        }
}

__global__ __launch_bounds__(256) void proj3(
    const bf16* __restrict__ qh, const bf16* __restrict__ ql,
    const bf16* __restrict__ xh, const bf16* __restrict__ xl,
    const bf16* __restrict__ wqh, const bf16* __restrict__ wql,
    const bf16* __restrict__ wkh, const bf16* __restrict__ wkl,
    const bf16* __restrict__ wvh, const bf16* __restrict__ wvl,
    const float* __restrict__ bq, const float* __restrict__ bk, const float* __restrict__ bv,
    bf16* __restrict__ Qh, bf16* __restrict__ Ql,
    bf16* __restrict__ Kh, bf16* __restrict__ Kl,
    bf16* __restrict__ Vh, bf16* __restrict__ Vl)
{
    extern __shared__ char sm[];
    int z = blockIdx.z;
    const bf16* Ah = (z == 0) ? qh : xh;
    const bf16* Al = (z == 0) ? ql : xl;
    const bf16* Bh = (z == 0) ? wqh : (z == 1) ? wkh : wvh;
    const bf16* Bl = (z == 0) ? wql : (z == 1) ? wkl : wvl;
    const float* bias = (z == 0) ? bq : (z == 1) ? bk : bv;
    bf16* Ch = (z == 0) ? Qh : (z == 1) ? Kh : Vh;
    bf16* Cl = (z == 0) ? Ql : (z == 1) ? Kl : Vl;
    hgemm_body(Ah, Al, Bh, Bl, bias, nullptr, Ch, Cl, 1024, 1024, 1024, 1024, sm);
}

__global__ __launch_bounds__(256) void hgemm_out(
    const bf16* __restrict__ Ah, const bf16* __restrict__ Al,
    const bf16* __restrict__ Bh, const bf16* __restrict__ Bl,
    const float* __restrict__ bias, float* __restrict__ Cf)
{
    extern __shared__ char sm[];
    hgemm_body(Ah, Al, Bh, Bl, bias, Cf, nullptr, nullptr, 1024, 1024, 1024, 1024, sm);
}

// ---------------------------------------------------------------------------
// vtrans: V bf16 hi+lo -> per (b,h) [64 d][2048 tok], fp16 single (rn of sum)
// ---------------------------------------------------------------------------
__global__ __launch_bounds__(256) void vtrans(
    const bf16* __restrict__ Vh, const bf16* __restrict__ Vl,
    __half* __restrict__ Th) {
    __shared__ bf16 sh[64][72], sl[64][72];
    int t = threadIdx.x, tt = blockIdx.x, bh = blockIdx.y;
    int b = bh >> 4, h = bh & 15;
    const bf16* srch = Vh + ((long)b * 2048 + tt * 64) * 1024 + h * 64;
    const bf16* srcl = Vl + ((long)b * 2048 + tt * 64) * 1024 + h * 64;
#pragma unroll
    for (int i = 0; i < 2; i++) {
        int s = t + 256 * i, row = s >> 3, seg = s & 7;
        *(uint4*)&sh[row][seg * 8] = *(const uint4*)(srch + (long)row * 1024 + seg * 8);
        *(uint4*)&sl[row][seg * 8] = *(const uint4*)(srcl + (long)row * 1024 + seg * 8);
    }
    __syncthreads();
    __half* dh = Th + (long)bh * 64 * 2048 + tt * 64;
#pragma unroll
    for (int i = 0; i < 2; i++) {
        int s = t + 256 * i, d = s >> 3, seg = s & 7;
        __align__(16) __half th[8];
#pragma unroll
        for (int j = 0; j < 8; j++) {
            float f = __bfloat162float(sh[seg * 8 + j][d]) + __bfloat162float(sl[seg * 8 + j][d]);
            th[j] = __float2half_rn(f);
        }
        *(uint4*)(dh + (long)d * 2048 + seg * 8) = *(uint4*)th;
    }
}

// ---------------------------------------------------------------------------
// fused_attn (round-14 + smem mask + log-trick):
// 256 threads, 64-q tile, 64-wide K tiles, 2 CTAs/SM, Q frags hoisted.
// QK: bf16 3-product. PV: P fp16 x V fp16 (single product).
// smem (bytes), tiles stride 144:
//   Q hi @0, Q lo @9216
//   K buf0 @18432 (hi,lo), buf1 @36864
//   P fp16 @55296 (9216) | V fp16 @64512 (9216)
//   part @73728 (256 f), linvs @74752 (64 f), msk @75008 (2048 f)
// total 83200 -> 2 CTAs/SM
// ---------------------------------------------------------------------------
#define FQ_H  0
#define FQ_L  9216
#define FKBUF(b) (18432 + (b) * 18432)
#define FP_H  55296
#define FV_H  64512
#define FPART 73728
#define FINVS 74752
#define FMSK  75008
#define SM_FUSED 83200

__global__ __launch_bounds__(256, 2) void fused_attn(
    const bf16* __restrict__ Qh, const bf16* __restrict__ Ql,
    const bf16* __restrict__ Kh, const bf16* __restrict__ Kl,
    const __half* __restrict__ Vth,
    const float* __restrict__ mask,
    float* __restrict__ A, bf16* __restrict__ Bh, bf16* __restrict__ Bl)
{
    extern __shared__ char sm[];
    uint32_t sb = smem_u32(sm);
    int t = threadIdx.x, lane = t & 31, wid = t >> 5;
    int wm = wid & 1, wn = wid >> 1;          // 2m x 4n; warp tile 32q x 16k
    int qt = blockIdx.x, bh = blockIdx.y;
    int b = bh >> 4, h = bh & 15;

    const bf16* qh = Qh + ((long)b * 2048 + qt * 64) * 1024 + h * 64;
    const bf16* ql = Ql + ((long)b * 2048 + qt * 64) * 1024 + h * 64;
    const bf16* kh = Kh + (long)b * 2048 * 1024 + h * 64;
    const bf16* kl = Kl + (long)b * 2048 * 1024 + h * 64;
    const __half* vth = Vth + (long)bh * 64 * 2048;
    float* Abh = A + ((long)bh * 2048 + qt * 64) * 2048;
    const float* mrow = mask + (long)b * 2048;

    float* part  = (float*)(sm + FPART);
    float* linvs = (float*)(sm + FINVS);
    float* msk   = (float*)(sm + FMSK);

#define KISSUE(kt_, buf_) do {                                                   \
    int _kt = (kt_); uint32_t _kb = sb + FKBUF(buf_);                            \
    _Pragma("unroll")                                                            \
    for (int i = 0; i < 4; i++) {                                                \
        int w = t + 256 * i;                                                     \
        int tile = w >> 9, inner = w & 511;                                      \
        int row = inner >> 3, sg = inner & 7;                                    \
        const bf16* src = (tile ? kl : kh) + (long)(_kt * 64 + row) * 1024 + sg * 8; \
        CP16(_kb + tile * 9216 + row * 144 + sg * 16, src);                      \
    }                                                                            \
    CPCOMMIT();                                                                  \
} while (0)

#define VISSUE(kt_) do {                                                         \
    int _kt = (kt_);                                                             \
    _Pragma("unroll")                                                            \
    for (int i = 0; i < 2; i++) {                                                \
        int w = t + 256 * i;                                                     \
        int row = w >> 3, sg = w & 7;                                            \
        const __half* src = vth + (long)row * 2048 + _kt * 64 + sg * 8;          \
        CP16(sb + FV_H + row * 144 + sg * 16, src);                              \
    }                                                                            \
    CPCOMMIT();                                                                  \
} while (0)

    // prologue: K(0) async, Q tiles plain, mask-add precomputed to smem
    KISSUE(0, 0);
#pragma unroll
    for (int i = 0; i < 4; i++) {
        int w = t + 256 * i;
        int tile = w >> 9, inner = w & 511;
        int row = inner >> 3, sg = inner & 7;
        const bf16* src = (tile ? ql : qh) + (long)row * 1024 + sg * 8;
        *(uint4*)(sm + (tile ? FQ_L : FQ_H) + row * 144 + sg * 16) = *(const uint4*)src;
    }
#pragma unroll
    for (int j = 0; j < 8; j++) {
        int idx = t + 256 * j;
        msk[idx] = (1.0f - mrow[idx]) * (-1e9f);
    }
    __syncthreads();   // Q + msk visible to all warps

    // hoist Q fragments: 2 mt x 4 k4 x 4 regs, hi + lo
    uint32_t qfh[2][4][4], qfl[2][4][4];
#pragma unroll
    for (int mt = 0; mt < 2; mt++)
#pragma unroll
        for (int k4 = 0; k4 < 4; k4++) {
            ldsmA(qfh[mt][k4], sb + FQ_H, wm * 32 + mt * 16, k4 * 16, 144, lane);
            ldsmA(qfl[mt][k4], sb + FQ_L, wm * 32 + mt * 16, k4 * 16, 144, lane);
        }

    // ---------------- pass A: rowsum only ----------------
    float rs[4] = {0.f, 0.f, 0.f, 0.f};
    for (int kt = 0; kt < 32; kt++) {
        CPWAIT(0);
        __syncthreads();
        if (kt + 1 < 32) KISSUE(kt + 1, (kt + 1) & 1);

        uint32_t kb = sb + FKBUF(kt & 1);
        float acc[2][2][4] = {};
#pragma unroll
        for (int k4 = 0; k4 < 4; k4++) {
            uint32_t bhf[4], blf[4];
            ldsmB(bhf, kb,        wn * 16, k4 * 16, 144, lane);
            ldsmB(blf, kb + 9216, wn * 16, k4 * 16, 144, lane);
#pragma unroll
            for (int mt = 0; mt < 2; mt++) {
                mma3(acc[mt][0], qfh[mt][k4], qfl[mt][k4], &bhf[0], &blf[0]);
                mma3(acc[mt][1], qfh[mt][k4], qfl[mt][k4], &bhf[2], &blf[2]);
            }
        }
#pragma unroll
        for (int nt = 0; nt < 2; nt++) {
            int cl = kt * 64 + wn * 16 + nt * 8 + 2 * (lane & 3);
            float m0v = msk[cl], m1v = msk[cl + 1];
#pragma unroll
            for (int mt = 0; mt < 2; mt++) {
                float* cc = acc[mt][nt];
                rs[mt * 2 + 0] += __expf(cc[0] + m0v) + __expf(cc[1] + m1v);
                rs[mt * 2 + 1] += __expf(cc[2] + m0v) + __expf(cc[3] + m1v);
            }
        }
    }

    KISSUE(0, 0);     // K(0) for pass B

    // reduce rowsum -> linvs[64] = -log(rowsum)
#pragma unroll
    for (int i = 0; i < 4; i++) {
        rs[i] += __shfl_xor_sync(0xffffffffu, rs[i], 1);
        rs[i] += __shfl_xor_sync(0xffffffffu, rs[i], 2);
    }
    __syncthreads();
    if ((lane & 3) == 0) {
#pragma unroll
        for (int mt = 0; mt < 2; mt++)
#pragma unroll
            for (int hf = 0; hf < 2; hf++)
                part[wn * 64 + wm * 32 + mt * 16 + hf * 8 + (lane >> 2)] = rs[mt * 2 + hf];
    }
    __syncthreads();
    if (t < 64)
        linvs[t] = -__logf(part[t] + part[64 + t] + part[128 + t] + part[192 + t]);
    __syncthreads();

    float linvr[2][2];
#pragma unroll
    for (int mt = 0; mt < 2; mt++) {
        linvr[mt][0] = linvs[wm * 32 + mt * 16 + (lane >> 2)];
        linvr[mt][1] = linvs[wm * 32 + mt * 16 + 8 + (lane >> 2)];
    }

    // ---------------- pass B ----------------
    float oacc[2][2][4] = {};
    for (int kt = 0; kt < 32; kt++) {
        CPWAIT(0);
        __syncthreads();                   // K(kt) ready; prior P/V reads done
        VISSUE(kt);                        // V first (released by wait_group 1)
        if (kt + 1 < 32) KISSUE(kt + 1, (kt + 1) & 1);

        uint32_t kb = sb + FKBUF(kt & 1);
        float acc[2][2][4] = {};
#pragma unroll
        for (int k4 = 0; k4 < 4; k4++) {
            uint32_t bhf[4], blf[4];
            ldsmB(bhf, kb,        wn * 16, k4 * 16, 144, lane);
            ldsmB(blf, kb + 9216, wn * 16, k4 * 16, 144, lane);
#pragma unroll
            for (int mt = 0; mt < 2; mt++) {
                mma3(acc[mt][0], qfh[mt][k4], qfl[mt][k4], &bhf[0], &blf[0]);
                mma3(acc[mt][1], qfh[mt][k4], qfl[mt][k4], &bhf[2], &blf[2]);
            }
        }

        // epilogue: attn = exp(s + maskadd + linv)  (log-trick, no mul)
#pragma unroll
        for (int nt = 0; nt < 2; nt++) {
            int cl = wn * 16 + nt * 8 + 2 * (lane & 3);
            int gc = kt * 64 + cl;
            float m0v = msk[gc], m1v = msk[gc + 1];
#pragma unroll
            for (int mt = 0; mt < 2; mt++) {
                float* cc = acc[mt][nt];
                int r0 = wm * 32 + mt * 16 + (lane >> 2);
                float e0 = __expf(cc[0] + m0v + linvr[mt][0]);
                float e1 = __expf(cc[1] + m1v + linvr[mt][0]);
                float e2 = __expf(cc[2] + m0v + linvr[mt][1]);
                float e3 = __expf(cc[3] + m1v + linvr[mt][1]);
                *(float2*)(Abh + (long)r0 * 2048 + gc)       = make_float2(e0, e1);
                *(float2*)(Abh + (long)(r0 + 8) * 2048 + gc) = make_float2(e2, e3);
                smem_h2f16(sm + FP_H + r0 * 144 + cl * 2, e0, e1);
                smem_h2f16(sm + FP_H + (r0 + 8) * 144 + cl * 2, e2, e3);
            }
        }

        if (kt + 1 < 32) { CPWAIT(1); } else { CPWAIT(0); }
        __syncthreads();                   // V(kt) + P visible

        // O += P(fp16) · V(fp16)^T  (single product)
#pragma unroll
        for (int k4 = 0; k4 < 4; k4++) {
            uint32_t ah[2][4], bhf[4];
#pragma unroll
            for (int mt = 0; mt < 2; mt++)
                ldsmA(ah[mt], sb + FP_H, wm * 32 + mt * 16, k4 * 16, 144, lane);
            ldsmB(bhf, sb + FV_H, wn * 16, k4 * 16, 144, lane);
#pragma unroll
            for (int mt = 0; mt < 2; mt++) {
                mma16816h(oacc[mt][0], ah[mt], &bhf[0]);
                mma16816h(oacc[mt][1], ah[mt], &bhf[2]);
            }
        }
    }

    // write blended split [b, q, h*64+d]
#pragma unroll
    for (int mt = 0; mt < 2; mt++)
#pragma unroll
        for (int nt = 0; nt < 2; nt++) {
            float* cc = oacc[mt][nt];
            long r0 = (long)b * 2048 + qt * 64 + wm * 32 + mt * 16 + (lane >> 2);
            int col = h * 64 + wn * 16 + nt * 8 + 2 * (lane & 3);
            store_split2(Bh, Bl, r0 * 1024 + col, cc[0], cc[1]);
            store_split2(Bh, Bl, (r0 + 8) * 1024 + col, cc[2], cc[3]);
        }
}

// ===========================================================================
extern "C" void kernel_launch(void* const* d_in, const int* in_sizes, int n_in,
                              void* d_out, int out_size) {
    (void)in_sizes; (void)n_in;
    const float* query        = (const float*)d_in[0];
    const float* input_embeds = (const float*)d_in[1];
    const float* mask         = (const float*)d_in[2];
    const float* wq_w = (const float*)d_in[3];
    const float* wq_b = (const float*)d_in[4];
    const float* wk_w = (const float*)d_in[5];
    const float* wk_b = (const float*)d_in[6];
    const float* wv_w = (const float*)d_in[7];
    const float* wv_b = (const float*)d_in[8];
    const float* wo_w = (const float*)d_in[9];
    const float* wo_b = (const float*)d_in[10];
    float* out = (float*)d_out;

    bf16 *qh, *ql, *xh, *xl, *wqh, *wql, *wkh, *wkl, *wvh, *wvl, *woh, *wol;
    bf16 *Qh, *Ql, *Kh, *Kl, *Vh, *Vl, *Bh, *Bl;
    __half *Vth16;
    float *attn_scratch;
    cudaGetSymbolAddress((void**)&qh, g_qh);   cudaGetSymbolAddress((void**)&ql, g_ql);
    cudaGetSymbolAddress((void**)&xh, g_xh);   cudaGetSymbolAddress((void**)&xl, g_xl);
    cudaGetSymbolAddress((void**)&wqh, g_wqh); cudaGetSymbolAddress((void**)&wql, g_wql);
    cudaGetSymbolAddress((void**)&wkh, g_wkh); cudaGetSymbolAddress((void**)&wkl, g_wkl);
    cudaGetSymbolAddress((void**)&wvh, g_wvh); cudaGetSymbolAddress((void**)&wvl, g_wvl);
    cudaGetSymbolAddress((void**)&woh, g_woh); cudaGetSymbolAddress((void**)&wol, g_wol);
    cudaGetSymbolAddress((void**)&Qh, g_Qh);   cudaGetSymbolAddress((void**)&Ql, g_Ql);
    cudaGetSymbolAddress((void**)&Kh, g_Kh);   cudaGetSymbolAddress((void**)&Kl, g_Kl);
    cudaGetSymbolAddress((void**)&Vh, g_Vh);   cudaGetSymbolAddress((void**)&Vl, g_Vl);
    cudaGetSymbolAddress((void**)&Vth16, g_Vth16);
    cudaGetSymbolAddress((void**)&Bh, g_Bh);   cudaGetSymbolAddress((void**)&Bl, g_Bl);
    cudaGetSymbolAddress((void**)&attn_scratch, g_attn);

    const long OUT_E = 4194304L, ATTN_E = 134217728L;
    float* attn = ((long)out_size >= OUT_E + ATTN_E) ? (out + OUT_E) : attn_scratch;

    const int SM_GEMM = 81920;
    cudaFuncSetAttribute(proj3,      cudaFuncAttributeMaxDynamicSharedMemorySize, SM_GEMM);
    cudaFuncSetAttribute(hgemm_out,  cudaFuncAttributeMaxDynamicSharedMemorySize, SM_GEMM);
    cudaFuncSetAttribute(fused_attn, cudaFuncAttributeMaxDynamicSharedMemorySize, SM_FUSED);

    cvt_all<<<12288, 256>>>(query, input_embeds, wq_w, wk_w, wv_w, wo_w,
                            qh, ql, xh, xl, wqh, wql, wkh, wkl, wvh, wvl, woh, wol);

    proj3<<<dim3(8, 32, 3), 256, SM_GEMM>>>(qh, ql, xh, xl,
                                            wqh, wql, wkh, wkl, wvh, wvl,
                                            wq_b, wk_b, wv_b,
                                            Qh, Ql, Kh, Kl, Vh, Vl);

    vtrans<<<dim3(32, 32), 256>>>(Vh, Vl, Vth16);

    fused_attn<<<dim3(32, 32), 256, SM_FUSED>>>(Qh, Ql, Kh, Kl, Vth16, mask,
                                                attn, Bh, Bl);

    hgemm_out<<<dim3(8, 32), 256, SM_GEMM>>>(Bh, Bl, woh, wol, wo_b, out);
}

// round 16
// speedup vs baseline: 1.2607x; 1.1335x over previous
#include <cuda_runtime.h>
#include <cuda_bf16.h>
#include <cuda_fp16.h>
#include <cstdint>

typedef __nv_bfloat16 bf16;

// ---------------------------------------------------------------------------
static __device__ __forceinline__ uint32_t smem_u32(const void* p) {
    uint32_t a;
    asm("{ .reg .u64 t; cvta.to.shared.u64 t, %1; cvt.u32.u64 %0, t; }" : "=r"(a) : "l"(p));
    return a;
}
static __device__ __forceinline__ void mma16816(float* c, const uint32_t* a, const uint32_t* b) {
    asm volatile("mma.sync.aligned.m16n8k16.row.col.f32.bf16.bf16.f32 "
        "{%0,%1,%2,%3}, {%4,%5,%6,%7}, {%8,%9}, {%0,%1,%2,%3};"
        : "+f"(c[0]), "+f"(c[1]), "+f"(c[2]), "+f"(c[3])
        : "r"(a[0]), "r"(a[1]), "r"(a[2]), "r"(a[3]), "r"(b[0]), "r"(b[1]));
}
static __device__ __forceinline__ void mma16816h(float* c, const uint32_t* a, const uint32_t* b) {
    asm volatile("mma.sync.aligned.m16n8k16.row.col.f32.f16.f16.f32 "
        "{%0,%1,%2,%3}, {%4,%5,%6,%7}, {%8,%9}, {%0,%1,%2,%3};"
        : "+f"(c[0]), "+f"(c[1]), "+f"(c[2]), "+f"(c[3])
        : "r"(a[0]), "r"(a[1]), "r"(a[2]), "r"(a[3]), "r"(b[0]), "r"(b[1]));
}
static __device__ __forceinline__ void mma3(float* c, const uint32_t* ah, const uint32_t* al,
                                            const uint32_t* bh, const uint32_t* bl) {
    mma16816(c, ah, bh); mma16816(c, ah, bl); mma16816(c, al, bh);
}
static __device__ __forceinline__ void ldsm4(uint32_t* r, uint32_t a) {
    asm volatile("ldmatrix.sync.aligned.m8n8.x4.shared.b16 {%0,%1,%2,%3}, [%4];"
        : "=r"(r[0]), "=r"(r[1]), "=r"(r[2]), "=r"(r[3]) : "r"(a));
}
static __device__ __forceinline__ void ldsmA(uint32_t* r, uint32_t base, int m0, int k0, int sbytes, int lane) {
    ldsm4(r, base + (uint32_t)((m0 + (lane & 7) + ((lane >> 3) & 1) * 8) * sbytes
                               + (k0 + ((lane >> 4) << 3)) * 2));
}
static __device__ __forceinline__ void ldsmB(uint32_t* r, uint32_t base, int n0, int k0, int sbytes, int lane) {
    ldsm4(r, base + (uint32_t)((n0 + (lane & 7) + ((lane >> 4) << 3)) * sbytes
                               + (k0 + (((lane >> 3) & 1) << 3)) * 2));
}
#define CP16(sm_, gp_) asm volatile("cp.async.cg.shared.global [%0], [%1], 16;" :: "r"(sm_), "l"(gp_))
#define CPCOMMIT()     asm volatile("cp.async.commit_group;")
#define CPWAIT(n)      asm volatile("cp.async.wait_group %0;" :: "n"(n))

static __device__ __forceinline__ void store_split2(bf16* Ch, bf16* Cl, long off, float x, float y) {
    __align__(4) bf16 h[2] = {__float2bfloat16(x), __float2bfloat16(y)};
    __align__(4) bf16 l[2] = {__float2bfloat16(x - __bfloat162float(h[0])),
                              __float2bfloat16(y - __bfloat162float(h[1]))};
    *(uint32_t*)(Ch + off) = *(uint32_t*)h;
    *(uint32_t*)(Cl + off) = *(uint32_t*)l;
}
static __device__ __forceinline__ void smem_h2f16(char* p, float x, float y) {
    __half2 h = __floats2half2_rn(x, y);
    *(uint32_t*)p = *(uint32_t*)&h;
}

// ---------------- scratch ----------------
__device__ bf16 g_qh[4194304], g_ql[4194304];
__device__ bf16 g_xh[4194304], g_xl[4194304];
__device__ __half g_x16[4194304];                 // input_embeds fp16 (for V proj)
__device__ bf16 g_wqh[1048576], g_wql[1048576];
__device__ bf16 g_wkh[1048576], g_wkl[1048576];
__device__ __half g_wv16[1048576];                // wv fp16 (for V proj)
__device__ bf16 g_woh[1048576], g_wol[1048576];
__device__ bf16 g_Qh[4194304], g_Ql[4194304];
__device__ bf16 g_Kh[4194304], g_Kl[4194304];
__device__ __half g_V16[4194304];                 // V fp16 [4096 tok, 1024]
__device__ __half g_Vth16[4194304];               // V^T fp16: [bh][64 d][2048 tok]
__device__ bf16 g_Bh[4194304], g_Bl[4194304];
__device__ float g_attn[134217728];

// ---------------- merged converts ----------------
// q -> bf16 pair; x -> bf16 pair + fp16; wq,wk,wo -> bf16 pair; wv -> fp16 only
__global__ __launch_bounds__(256) void cvt_all(
    const float* __restrict__ s0, const float* __restrict__ s1,
    const float* __restrict__ s2, const float* __restrict__ s3,
    const float* __restrict__ s4, const float* __restrict__ s5,
    bf16* __restrict__ h0, bf16* __restrict__ l0,
    bf16* __restrict__ h1, bf16* __restrict__ l1, __half* __restrict__ x16,
    bf16* __restrict__ h2, bf16* __restrict__ l2,
    bf16* __restrict__ h3, bf16* __restrict__ l3,
    __half* __restrict__ wv16,
    bf16* __restrict__ h5, bf16* __restrict__ l5)
{
    long i = (long)blockIdx.x * 256 + threadIdx.x;   // < 3145728
    const float* src; bf16 *h = nullptr, *l = nullptr; __half* f16 = nullptr; long li;
    if (i < 1048576)      { src = s0; h = h0; l = l0; li = i; }
    else if (i < 2097152) { src = s1; h = h1; l = l1; f16 = x16; li = i - 1048576; }
    else {
        long j = i - 2097152;
        int w = (int)(j >> 18);
        li = j & 262143;
        if (w == 0)      { src = s2; h = h2; l = l2; }
        else if (w == 1) { src = s3; h = h3; l = l3; }
        else if (w == 2) { src = s4; f16 = wv16; }
        else             { src = s5; h = h5; l = l5; }
    }
    float4 v = ((const float4*)src)[li];
    float f[4] = {v.x, v.y, v.z, v.w};
    if (h) {
        __align__(8) bf16 hv[4], lv[4];
#pragma unroll
        for (int j = 0; j < 4; j++) {
            hv[j] = __float2bfloat16(f[j]);
            lv[j] = __float2bfloat16(f[j] - __bfloat162float(hv[j]));
        }
        ((uint2*)h)[li] = *(uint2*)hv;
        ((uint2*)l)[li] = *(uint2*)lv;
    }
    if (f16) {
        __align__(8) __half g16[4];
#pragma unroll
        for (int j = 0; j < 4; j++) g16[j] = __float2half_rn(f[j]);
        ((uint2*)f16)[li] = *(uint2*)g16;
    }
}

// ---------------------------------------------------------------------------
// hgemm body (proven): bf16x3, 256 threads, 4m x 2n, 128x128, BK=32
// ---------------------------------------------------------------------------
static __device__ __forceinline__ void hgemm_body(
    const bf16* __restrict__ Ah, const bf16* __restrict__ Al,
    const bf16* __restrict__ Bh, const bf16* __restrict__ Bl,
    const float* __restrict__ bias, float* __restrict__ Cf,
    bf16* __restrict__ Ch, bf16* __restrict__ Cl,
    int K, int lda, int ldb, int ldc, char* sm)
{
    uint32_t sb = smem_u32(sm);
    int t = threadIdx.x, lane = t & 31, wid = t >> 5;
    int wm = wid & 3, wn = wid >> 2;
    long m0 = blockIdx.y * 128, n0 = blockIdx.x * 128;

    const bf16* g0 = Ah + m0 * lda;
    const bf16* g1 = Al + m0 * lda;
    const bf16* g2 = Bh + n0 * ldb;
    const bf16* g3 = Bl + n0 * ldb;

#define G_ISSUE(c_, buf_) do {                                                  \
    int _c = (c_); uint32_t _bs = sb + (buf_) * 40960;                          \
    _Pragma("unroll")                                                           \
    for (int i = 0; i < 8; i++) {                                               \
        const int tile = i >> 1;                                                \
        int w = t + 256 * (i & 1);                                               \
        int row = w >> 2, sg = w & 3;                                           \
        const bf16* gp = (tile == 0 ? g0 : tile == 1 ? g1 : tile == 2 ? g2 : g3)\
            + (long)row * (tile < 2 ? lda : ldb) + _c * 32 + sg * 8;            \
        CP16(_bs + tile * 10240 + row * 80 + sg * 16, gp);                      \
    }                                                                           \
    CPCOMMIT();                                                                 \
} while (0)

    float acc[2][8][4] = {};
    int nc = K >> 5;
    G_ISSUE(0, 0);
    G_ISSUE(1, 1);
    for (int c = 0; c < nc; c++) {
        if (c + 1 < nc) { CPWAIT(1); } else { CPWAIT(0); }
        __syncthreads();
        uint32_t bAh = sb + (c & 1) * 40960, bAl = bAh + 10240;
        uint32_t bBh = bAh + 20480, bBl = bAh + 30720;
#pragma unroll
        for (int k0 = 0; k0 < 32; k0 += 16) {
            uint32_t ah[2][4], al[2][4], bhf[4][4], blf[4][4];
#pragma unroll
            for (int mt = 0; mt < 2; mt++) {
                ldsmA(ah[mt], bAh, wm * 32 + mt * 16, k0, 80, lane);
                ldsmA(al[mt], bAl, wm * 32 + mt * 16, k0, 80, lane);
            }
#pragma unroll
            for (int p = 0; p < 4; p++) {
                ldsmB(bhf[p], bBh, wn * 64 + p * 16, k0, 80, lane);
                ldsmB(blf[p], bBl, wn * 64 + p * 16, k0, 80, lane);
            }
#pragma unroll
            for (int mt = 0; mt < 2; mt++)
#pragma unroll
                for (int p = 0; p < 4; p++) {
                    mma3(acc[mt][p * 2],     ah[mt], al[mt], &bhf[p][0], &blf[p][0]);
                    mma3(acc[mt][p * 2 + 1], ah[mt], al[mt], &bhf[p][2], &blf[p][2]);
                }
        }
        __syncthreads();
        if (c + 2 < nc) G_ISSUE(c + 2, c & 1);
    }
#undef G_ISSUE

#pragma unroll
    for (int mt = 0; mt < 2; mt++)
#pragma unroll
        for (int nt = 0; nt < 8; nt++) {
            float* cc = acc[mt][nt];
            long r0 = m0 + wm * 32 + mt * 16 + (lane >> 2);
            int col = (int)n0 + wn * 64 + nt * 8 + 2 * (lane & 3);
            float b0 = bias[col], b1 = bias[col + 1];
            float f0 = cc[0] + b0, f1 = cc[1] + b1, f2 = cc[2] + b0, f3 = cc[3] + b1;
            if (Cf) {
                *(float2*)(Cf + r0 * ldc + col) = make_float2(f0, f1);
                *(float2*)(Cf + (r0 + 8) * ldc + col) = make_float2(f2, f3);
            }
            if (Ch) {
                store_split2(Ch, Cl, r0 * ldc + col, f0, f1);
                store_split2(Ch, Cl, (r0 + 8) * ldc + col, f2, f3);
            }
        }
}

// Q/K projections (bf16x3)
__global__ __launch_bounds__(256) void projQK(
    const bf16* __restrict__ qh, const bf16* __restrict__ ql,
    const bf16* __restrict__ xh, const bf16* __restrict__ xl,
    const bf16* __restrict__ wqh, const bf16* __restrict__ wql,
    const bf16* __restrict__ wkh, const bf16* __restrict__ wkl,
    const float* __restrict__ bq, const float* __restrict__ bk,
    bf16* __restrict__ Qh, bf16* __restrict__ Ql,
    bf16* __restrict__ Kh, bf16* __restrict__ Kl)
{
    extern __shared__ char sm[];
    int z = blockIdx.z;
    const bf16* Ah = (z == 0) ? qh : xh;
    const bf16* Al = (z == 0) ? ql : xl;
    const bf16* Bh = (z == 0) ? wqh : wkh;
    const bf16* Bl = (z == 0) ? wql : wkl;
    const float* bias = (z == 0) ? bq : bk;
    bf16* Ch = (z == 0) ? Qh : Kh;
    bf16* Cl = (z == 0) ? Ql : Kl;
    hgemm_body(Ah, Al, Bh, Bl, bias, nullptr, Ch, Cl, 1024, 1024, 1024, 1024, sm);
}

__global__ __launch_bounds__(256) void hgemm_out(
    const bf16* __restrict__ Ah, const bf16* __restrict__ Al,
    const bf16* __restrict__ Bh, const bf16* __restrict__ Bl,
    const float* __restrict__ bias, float* __restrict__ Cf)
{
    extern __shared__ char sm[];
    hgemm_body(Ah, Al, Bh, Bl, bias, Cf, nullptr, nullptr, 1024, 1024, 1024, 1024, sm);
}

// ---------------------------------------------------------------------------
// projV: V16 = x16 @ wv16^T + bv  (single-product fp16, fp32 accum)
// 128x128 tile, BK=32, cp.async double-buffered, smem 40960B
// ---------------------------------------------------------------------------
__global__ __launch_bounds__(256) void projV(
    const __half* __restrict__ x16, const __half* __restrict__ wv16,
    const float* __restrict__ bv, __half* __restrict__ V16)
{
    extern __shared__ char sm[];
    uint32_t sb = smem_u32(sm);
    int t = threadIdx.x, lane = t & 31, wid = t >> 5;
    int wm = wid & 3, wn = wid >> 2;
    long m0 = blockIdx.y * 128, n0 = blockIdx.x * 128;

    const __half* gA = x16 + m0 * 1024;
    const __half* gB = wv16 + n0 * 1024;

#define GV_ISSUE(c_, buf_) do {                                                 \
    int _c = (c_); uint32_t _bs = sb + (buf_) * 20480;                          \
    _Pragma("unroll")                                                           \
    for (int i = 0; i < 4; i++) {                                               \
        int w = t + 256 * i;                                                    \
        int tile = w >> 9, inner = w & 511;                                     \
        int row = inner >> 2, sg = inner & 3;                                   \
        const __half* gp = (tile ? gB : gA) + (long)row * 1024 + _c * 32 + sg * 8; \
        CP16(_bs + tile * 10240 + row * 80 + sg * 16, gp);                      \
    }                                                                           \
    CPCOMMIT();                                                                 \
} while (0)

    float acc[2][8][4] = {};
    GV_ISSUE(0, 0);
    GV_ISSUE(1, 1);
    for (int c = 0; c < 32; c++) {
        if (c + 1 < 32) { CPWAIT(1); } else { CPWAIT(0); }
        __syncthreads();
        uint32_t bA = sb + (c & 1) * 20480, bB = bA + 10240;
#pragma unroll
        for (int k0 = 0; k0 < 32; k0 += 16) {
            uint32_t ah[2][4], bf[4][4];
#pragma unroll
            for (int mt = 0; mt < 2; mt++)
                ldsmA(ah[mt], bA, wm * 32 + mt * 16, k0, 80, lane);
#pragma unroll
            for (int p = 0; p < 4; p++)
                ldsmB(bf[p], bB, wn * 64 + p * 16, k0, 80, lane);
#pragma unroll
            for (int mt = 0; mt < 2; mt++)
#pragma unroll
                for (int p = 0; p < 4; p++) {
                    mma16816h(acc[mt][p * 2],     ah[mt], &bf[p][0]);
                    mma16816h(acc[mt][p * 2 + 1], ah[mt], &bf[p][2]);
                }
        }
        __syncthreads();
        if (c + 2 < 32) GV_ISSUE(c + 2, c & 1);
    }
#undef GV_ISSUE

#pragma unroll
    for (int mt = 0; mt < 2; mt++)
#pragma unroll
        for (int nt = 0; nt < 8; nt++) {
            float* cc = acc[mt][nt];
            long r0 = m0 + wm * 32 + mt * 16 + (lane >> 2);
            int col = (int)n0 + wn * 64 + nt * 8 + 2 * (lane & 3);
            float b0 = bv[col], b1 = bv[col + 1];
            __half2 v0 = __floats2half2_rn(cc[0] + b0, cc[1] + b1);
            __half2 v1 = __floats2half2_rn(cc[2] + b0, cc[3] + b1);
            *(uint32_t*)(V16 + r0 * 1024 + col)       = *(uint32_t*)&v0;
            *(uint32_t*)(V16 + (r0 + 8) * 1024 + col) = *(uint32_t*)&v1;
        }
}

// ---------------------------------------------------------------------------
// vtrans: V16 fp16 [4096 tok,1024] -> per (b,h) [64 d][2048 tok] (exact copy)
// ---------------------------------------------------------------------------
__global__ __launch_bounds__(256) void vtrans(
    const __half* __restrict__ V16, __half* __restrict__ Th) {
    __shared__ __half sh[64][72];
    int t = threadIdx.x, tt = blockIdx.x, bh = blockIdx.y;
    int b = bh >> 4, h = bh & 15;
    const __half* src = V16 + ((long)b * 2048 + tt * 64) * 1024 + h * 64;
#pragma unroll
    for (int i = 0; i < 2; i++) {
        int s = t + 256 * i, row = s >> 3, seg = s & 7;
        *(uint4*)&sh[row][seg * 8] = *(const uint4*)(src + (long)row * 1024 + seg * 8);
    }
    __syncthreads();
    __half* dh = Th + (long)bh * 64 * 2048 + tt * 64;
#pragma unroll
    for (int i = 0; i < 2; i++) {
        int s = t + 256 * i, d = s >> 3, seg = s & 7;
        __align__(16) __half th[8];
#pragma unroll
        for (int j = 0; j < 8; j++) th[j] = sh[seg * 8 + j][d];
        *(uint4*)(dh + (long)d * 2048 + seg * 8) = *(uint4*)th;
    }
}

// ---------------------------------------------------------------------------
// fused_attn — UNCHANGED from round 15 (best measured)
// ---------------------------------------------------------------------------
#define FQ_H  0
#define FQ_L  9216
#define FKBUF(b) (18432 + (b) * 18432)
#define FP_H  55296
#define FV_H  64512
#define FPART 73728
#define FINVS 74752
#define FMSK  75008
#define SM_FUSED 83200

__global__ __launch_bounds__(256, 2) void fused_attn(
    const bf16* __restrict__ Qh, const bf16* __restrict__ Ql,
    const bf16* __restrict__ Kh, const bf16* __restrict__ Kl,
    const __half* __restrict__ Vth,
    const float* __restrict__ mask,
    float* __restrict__ A, bf16* __restrict__ Bh, bf16* __restrict__ Bl)
{
    extern __shared__ char sm[];
    uint32_t sb = smem_u32(sm);
    int t = threadIdx.x, lane = t & 31, wid = t >> 5;
    int wm = wid & 1, wn = wid >> 1;          // 2m x 4n; warp tile 32q x 16k
    int qt = blockIdx.x, bh = blockIdx.y;
    int b = bh >> 4, h = bh & 15;

    const bf16* qh = Qh + ((long)b * 2048 + qt * 64) * 1024 + h * 64;
    const bf16* ql = Ql + ((long)b * 2048 + qt * 64) * 1024 + h * 64;
    const bf16* kh = Kh + (long)b * 2048 * 1024 + h * 64;
    const bf16* kl = Kl + (long)b * 2048 * 1024 + h * 64;
    const __half* vth = Vth + (long)bh * 64 * 2048;
    float* Abh = A + ((long)bh * 2048 + qt * 64) * 2048;
    const float* mrow = mask + (long)b * 2048;

    float* part  = (float*)(sm + FPART);
    float* linvs = (float*)(sm + FINVS);
    float* msk   = (float*)(sm + FMSK);

#define KISSUE(kt_, buf_) do {                                                   \
    int _kt = (kt_); uint32_t _kb = sb + FKBUF(buf_);                            \
    _Pragma("unroll")                                                            \
    for (int i = 0; i < 4; i++) {                                                \
        int w = t + 256 * i;                                                     \
        int tile = w >> 9, inner = w & 511;                                      \
        int row = inner >> 3, sg = inner & 7;                                    \
        const bf16* src = (tile ? kl : kh) + (long)(_kt * 64 + row) * 1024 + sg * 8; \
        CP16(_kb + tile * 9216 + row * 144 + sg * 16, src);                      \
    }                                                                            \
    CPCOMMIT();                                                                  \
} while (0)

#define VISSUE(kt_) do {                                                         \
    int _kt = (kt_);                                                             \
    _Pragma("unroll")                                                            \
    for (int i = 0; i < 2; i++) {                                                \
        int w = t + 256 * i;                                                     \
        int row = w >> 3, sg = w & 7;                                            \
        const __half* src = vth + (long)row * 2048 + _kt * 64 + sg * 8;          \
        CP16(sb + FV_H + row * 144 + sg * 16, src);                              \
    }                                                                            \
    CPCOMMIT();                                                                  \
} while (0)

    // prologue: K(0) async, Q tiles plain, mask-add precomputed to smem
    KISSUE(0, 0);
#pragma unroll
    for (int i = 0; i < 4; i++) {
        int w = t + 256 * i;
        int tile = w >> 9, inner = w & 511;
        int row = inner >> 3, sg = inner & 7;
        const bf16* src = (tile ? ql : qh) + (long)row * 1024 + sg * 8;
        *(uint4*)(sm + (tile ? FQ_L : FQ_H) + row * 144 + sg * 16) = *(const uint4*)src;
    }
#pragma unroll
    for (int j = 0; j < 8; j++) {
        int idx = t + 256 * j;
        msk[idx] = (1.0f - mrow[idx]) * (-1e9f);
    }
    __syncthreads();

    uint32_t qfh[2][4][4], qfl[2][4][4];
#pragma unroll
    for (int mt = 0; mt < 2; mt++)
#pragma unroll
        for (int k4 = 0; k4 < 4; k4++) {
            ldsmA(qfh[mt][k4], sb + FQ_H, wm * 32 + mt * 16, k4 * 16, 144, lane);
            ldsmA(qfl[mt][k4], sb + FQ_L, wm * 32 + mt * 16, k4 * 16, 144, lane);
        }

    // ---------------- pass A: rowsum only ----------------
    float rs[4] = {0.f, 0.f, 0.f, 0.f};
    for (int kt = 0; kt < 32; kt++) {
        CPWAIT(0);
        __syncthreads();
        if (kt + 1 < 32) KISSUE(kt + 1, (kt + 1) & 1);

        uint32_t kb = sb + FKBUF(kt & 1);
        float acc[2][2][4] = {};
#pragma unroll
        for (int k4 = 0; k4 < 4; k4++) {
            uint32_t bhf[4], blf[4];
            ldsmB(bhf, kb,        wn * 16, k4 * 16, 144, lane);
            ldsmB(blf, kb + 9216, wn * 16, k4 * 16, 144, lane);
#pragma unroll
            for (int mt = 0; mt < 2; mt++) {
                mma3(acc[mt][0], qfh[mt][k4], qfl[mt][k4], &bhf[0], &blf[0]);
                mma3(acc[mt][1], qfh[mt][k4], qfl[mt][k4], &bhf[2], &blf[2]);
            }
        }
#pragma unroll
        for (int nt = 0; nt < 2; nt++) {
            int cl = kt * 64 + wn * 16 + nt * 8 + 2 * (lane & 3);
            float m0v = msk[cl], m1v = msk[cl + 1];
#pragma unroll
            for (int mt = 0; mt < 2; mt++) {
                float* cc = acc[mt][nt];
                rs[mt * 2 + 0] += __expf(cc[0] + m0v) + __expf(cc[1] + m1v);
                rs[mt * 2 + 1] += __expf(cc[2] + m0v) + __expf(cc[3] + m1v);
            }
        }
    }

    KISSUE(0, 0);     // K(0) for pass B

#pragma unroll
    for (int i = 0; i < 4; i++) {
        rs[i] += __shfl_xor_sync(0xffffffffu, rs[i], 1);
        rs[i] += __shfl_xor_sync(0xffffffffu, rs[i], 2);
    }
    __syncthreads();
    if ((lane & 3) == 0) {
#pragma unroll
        for (int mt = 0; mt < 2; mt++)
#pragma unroll
            for (int hf = 0; hf < 2; hf++)
                part[wn * 64 + wm * 32 + mt * 16 + hf * 8 + (lane >> 2)] = rs[mt * 2 + hf];
    }
    __syncthreads();
    if (t < 64)
        linvs[t] = -__logf(part[t] + part[64 + t] + part[128 + t] + part[192 + t]);
    __syncthreads();

    float linvr[2][2];
#pragma unroll
    for (int mt = 0; mt < 2; mt++) {
        linvr[mt][0] = linvs[wm * 32 + mt * 16 + (lane >> 2)];
        linvr[mt][1] = linvs[wm * 32 + mt * 16 + 8 + (lane >> 2)];
    }

    // ---------------- pass B ----------------
    float oacc[2][2][4] = {};
    for (int kt = 0; kt < 32; kt++) {
        CPWAIT(0);
        __syncthreads();
        VISSUE(kt);
        if (kt + 1 < 32) KISSUE(kt + 1, (kt + 1) & 1);

        uint32_t kb = sb + FKBUF(kt & 1);
        float acc[2][2][4] = {};
#pragma unroll
        for (int k4 = 0; k4 < 4; k4++) {
            uint32_t bhf[4], blf[4];
            ldsmB(bhf, kb,        wn * 16, k4 * 16, 144, lane);
            ldsmB(blf, kb + 9216, wn * 16, k4 * 16, 144, lane);
#pragma unroll
            for (int mt = 0; mt < 2; mt++) {
                mma3(acc[mt][0], qfh[mt][k4], qfl[mt][k4], &bhf[0], &blf[0]);
                mma3(acc[mt][1], qfh[mt][k4], qfl[mt][k4], &bhf[2], &blf[2]);
            }
        }

#pragma unroll
        for (int nt = 0; nt < 2; nt++) {
            int cl = wn * 16 + nt * 8 + 2 * (lane & 3);
            int gc = kt * 64 + cl;
            float m0v = msk[gc], m1v = msk[gc + 1];
#pragma unroll
            for (int mt = 0; mt < 2; mt++) {
                float* cc = acc[mt][nt];
                int r0 = wm * 32 + mt * 16 + (lane >> 2);
                float e0 = __expf(cc[0] + m0v + linvr[mt][0]);
                float e1 = __expf(cc[1] + m1v + linvr[mt][0]);
                float e2 = __expf(cc[2] + m0v + linvr[mt][1]);
                float e3 = __expf(cc[3] + m1v + linvr[mt][1]);
                *(float2*)(Abh + (long)r0 * 2048 + gc)       = make_float2(e0, e1);
                *(float2*)(Abh + (long)(r0 + 8) * 2048 + gc) = make_float2(e2, e3);
                smem_h2f16(sm + FP_H + r0 * 144 + cl * 2, e0, e1);
                smem_h2f16(sm + FP_H + (r0 + 8) * 144 + cl * 2, e2, e3);
            }
        }

        if (kt + 1 < 32) { CPWAIT(1); } else { CPWAIT(0); }
        __syncthreads();

#pragma unroll
        for (int k4 = 0; k4 < 4; k4++) {
            uint32_t ah[2][4], bhf[4];
#pragma unroll
            for (int mt = 0; mt < 2; mt++)
                ldsmA(ah[mt], sb + FP_H, wm * 32 + mt * 16, k4 * 16, 144, lane);
            ldsmB(bhf, sb + FV_H, wn * 16, k4 * 16, 144, lane);
#pragma unroll
            for (int mt = 0; mt < 2; mt++) {
                mma16816h(oacc[mt][0], ah[mt], &bhf[0]);
                mma16816h(oacc[mt][1], ah[mt], &bhf[2]);
            }
        }
    }

#pragma unroll
    for (int mt = 0; mt < 2; mt++)
#pragma unroll
        for (int nt = 0; nt < 2; nt++) {
            float* cc = oacc[mt][nt];
            long r0 = (long)b * 2048 + qt * 64 + wm * 32 + mt * 16 + (lane >> 2);
            int col = h * 64 + wn * 16 + nt * 8 + 2 * (lane & 3);
            store_split2(Bh, Bl, r0 * 1024 + col, cc[0], cc[1]);
            store_split2(Bh, Bl, (r0 + 8) * 1024 + col, cc[2], cc[3]);
        }
}

// ===========================================================================
extern "C" void kernel_launch(void* const* d_in, const int* in_sizes, int n_in,
                              void* d_out, int out_size) {
    (void)in_sizes; (void)n_in;
    const float* query        = (const float*)d_in[0];
    const float* input_embeds = (const float*)d_in[1];
    const float* mask         = (const float*)d_in[2];
    const float* wq_w = (const float*)d_in[3];
    const float* wq_b = (const float*)d_in[4];
    const float* wk_w = (const float*)d_in[5];
    const float* wk_b = (const float*)d_in[6];
    const float* wv_w = (const float*)d_in[7];
    const float* wv_b = (const float*)d_in[8];
    const float* wo_w = (const float*)d_in[9];
    const float* wo_b = (const float*)d_in[10];
    float* out = (float*)d_out;

    bf16 *qh, *ql, *xh, *xl, *wqh, *wql, *wkh, *wkl, *woh, *wol;
    bf16 *Qh, *Ql, *Kh, *Kl, *Bh, *Bl;
    __half *x16, *wv16, *V16, *Vth16;
    float *attn_scratch;
    cudaGetSymbolAddress((void**)&qh, g_qh);   cudaGetSymbolAddress((void**)&ql, g_ql);
    cudaGetSymbolAddress((void**)&xh, g_xh);   cudaGetSymbolAddress((void**)&xl, g_xl);
    cudaGetSymbolAddress((void**)&x16, g_x16);
    cudaGetSymbolAddress((void**)&wqh, g_wqh); cudaGetSymbolAddress((void**)&wql, g_wql);
    cudaGetSymbolAddress((void**)&wkh, g_wkh); cudaGetSymbolAddress((void**)&wkl, g_wkl);
    cudaGetSymbolAddress((void**)&wv16, g_wv16);
    cudaGetSymbolAddress((void**)&woh, g_woh); cudaGetSymbolAddress((void**)&wol, g_wol);
    cudaGetSymbolAddress((void**)&Qh, g_Qh);   cudaGetSymbolAddress((void**)&Ql, g_Ql);
    cudaGetSymbolAddress((void**)&Kh, g_Kh);   cudaGetSymbolAddress((void**)&Kl, g_Kl);
    cudaGetSymbolAddress((void**)&V16, g_V16);
    cudaGetSymbolAddress((void**)&Vth16, g_Vth16);
    cudaGetSymbolAddress((void**)&Bh, g_Bh);   cudaGetSymbolAddress((void**)&Bl, g_Bl);
    cudaGetSymbolAddress((void**)&attn_scratch, g_attn);

    const long OUT_E = 4194304L, ATTN_E = 134217728L;
    float* attn = ((long)out_size >= OUT_E + ATTN_E) ? (out + OUT_E) : attn_scratch;

    const int SM_GEMM = 81920, SM_PROJV = 40960;
    cudaFuncSetAttribute(projQK,     cudaFuncAttributeMaxDynamicSharedMemorySize, SM_GEMM);
    cudaFuncSetAttribute(hgemm_out,  cudaFuncAttributeMaxDynamicSharedMemorySize, SM_GEMM);
    cudaFuncSetAttribute(projV,      cudaFuncAttributeMaxDynamicSharedMemorySize, SM_PROJV);
    cudaFuncSetAttribute(fused_attn, cudaFuncAttributeMaxDynamicSharedMemorySize, SM_FUSED);

    cvt_all<<<12288, 256>>>(query, input_embeds, wq_w, wk_w, wv_w, wo_w,
                            qh, ql, xh, xl, x16, wqh, wql, wkh, wkl, wv16, woh, wol);

    projQK<<<dim3(8, 32, 2), 256, SM_GEMM>>>(qh, ql, xh, xl,
                                             wqh, wql, wkh, wkl,
                                             wq_b, wk_b, Qh, Ql, Kh, Kl);

    projV<<<dim3(8, 32), 256, SM_PROJV>>>(x16, wv16, wv_b, V16);

    vtrans<<<dim3(32, 32), 256>>>(V16, Vth16);

    fused_attn<<<dim3(32, 32), 256, SM_FUSED>>>(Qh, Ql, Kh, Kl, Vth16, mask,
                                                attn, Bh, Bl);

    hgemm_out<<<dim3(8, 32), 256, SM_GEMM>>>(Bh, Bl, woh, wol, wo_b, out);
}

// round 17
// speedup vs baseline: 1.3692x; 1.0861x over previous
#include <cuda_runtime.h>
#include <cuda_bf16.h>
#include <cuda_fp16.h>
#include <cstdint>

typedef __nv_bfloat16 bf16;

// ---------------------------------------------------------------------------
static __device__ __forceinline__ uint32_t smem_u32(const void* p) {
    uint32_t a;
    asm("{ .reg .u64 t; cvta.to.shared.u64 t, %1; cvt.u32.u64 %0, t; }" : "=r"(a) : "l"(p));
    return a;
}
static __device__ __forceinline__ void mma16816(float* c, const uint32_t* a, const uint32_t* b) {
    asm volatile("mma.sync.aligned.m16n8k16.row.col.f32.bf16.bf16.f32 "
        "{%0,%1,%2,%3}, {%4,%5,%6,%7}, {%8,%9}, {%0,%1,%2,%3};"
        : "+f"(c[0]), "+f"(c[1]), "+f"(c[2]), "+f"(c[3])
        : "r"(a[0]), "r"(a[1]), "r"(a[2]), "r"(a[3]), "r"(b[0]), "r"(b[1]));
}
static __device__ __forceinline__ void mma16816h(float* c, const uint32_t* a, const uint32_t* b) {
    asm volatile("mma.sync.aligned.m16n8k16.row.col.f32.f16.f16.f32 "
        "{%0,%1,%2,%3}, {%4,%5,%6,%7}, {%8,%9}, {%0,%1,%2,%3};"
        : "+f"(c[0]), "+f"(c[1]), "+f"(c[2]), "+f"(c[3])
        : "r"(a[0]), "r"(a[1]), "r"(a[2]), "r"(a[3]), "r"(b[0]), "r"(b[1]));
}
static __device__ __forceinline__ void mma3(float* c, const uint32_t* ah, const uint32_t* al,
                                            const uint32_t* bh, const uint32_t* bl) {
    mma16816(c, ah, bh); mma16816(c, ah, bl); mma16816(c, al, bh);
}
static __device__ __forceinline__ void ldsm4(uint32_t* r, uint32_t a) {
    asm volatile("ldmatrix.sync.aligned.m8n8.x4.shared.b16 {%0,%1,%2,%3}, [%4];"
        : "=r"(r[0]), "=r"(r[1]), "=r"(r[2]), "=r"(r[3]) : "r"(a));
}
static __device__ __forceinline__ void ldsmA(uint32_t* r, uint32_t base, int m0, int k0, int sbytes, int lane) {
    ldsm4(r, base + (uint32_t)((m0 + (lane & 7) + ((lane >> 3) & 1) * 8) * sbytes
                               + (k0 + ((lane >> 4) << 3)) * 2));
}
static __device__ __forceinline__ void ldsmB(uint32_t* r, uint32_t base, int n0, int k0, int sbytes, int lane) {
    ldsm4(r, base + (uint32_t)((n0 + (lane & 7) + ((lane >> 4) << 3)) * sbytes
                               + (k0 + (((lane >> 3) & 1) << 3)) * 2));
}
#define CP16(sm_, gp_) asm volatile("cp.async.cg.shared.global [%0], [%1], 16;" :: "r"(sm_), "l"(gp_))
#define CPCOMMIT()     asm volatile("cp.async.commit_group;")
#define CPWAIT(n)      asm volatile("cp.async.wait_group %0;" :: "n"(n))

static __device__ __forceinline__ void store_split2(bf16* Ch, bf16* Cl, long off, float x, float y) {
    __align__(4) bf16 h[2] = {__float2bfloat16(x), __float2bfloat16(y)};
    __align__(4) bf16 l[2] = {__float2bfloat16(x - __bfloat162float(h[0])),
                              __float2bfloat16(y - __bfloat162float(h[1]))};
    *(uint32_t*)(Ch + off) = *(uint32_t*)h;
    *(uint32_t*)(Cl + off) = *(uint32_t*)l;
}
static __device__ __forceinline__ void smem_h2f16(char* p, float x, float y) {
    __half2 h = __floats2half2_rn(x, y);
    *(uint32_t*)p = *(uint32_t*)&h;
}

// ---------------- scratch ----------------
__device__ bf16 g_qh[4194304], g_ql[4194304];
__device__ bf16 g_xh[4194304], g_xl[4194304];
__device__ __half g_x16[4194304];
__device__ bf16 g_wqh[1048576], g_wql[1048576];
__device__ bf16 g_wkh[1048576], g_wkl[1048576];
__device__ __half g_wv16[1048576];
__device__ __half g_woh16[1048576], g_wol16[1048576];   // split of wo*64
__device__ bf16 g_Qh[4194304], g_Ql[4194304];
__device__ bf16 g_Kh[4194304], g_Kl[4194304];
__device__ __half g_V16[4194304];
__device__ __half g_Vth16[4194304];               // V^T fp16: [bh][64 d][2048 tok]
__device__ __half g_B16[4194304];                 // blended fp16 [4096, 1024]
__device__ float g_attn[134217728];

// ---------------- merged converts ----------------
// q,wq,wk -> bf16 pair; x -> bf16 pair + fp16; wv -> fp16; wo -> fp16 pair (x64)
__global__ __launch_bounds__(256) void cvt_all(
    const float* __restrict__ s0, const float* __restrict__ s1,
    const float* __restrict__ s2, const float* __restrict__ s3,
    const float* __restrict__ s4, const float* __restrict__ s5,
    bf16* __restrict__ h0, bf16* __restrict__ l0,
    bf16* __restrict__ h1, bf16* __restrict__ l1, __half* __restrict__ x16,
    bf16* __restrict__ h2, bf16* __restrict__ l2,
    bf16* __restrict__ h3, bf16* __restrict__ l3,
    __half* __restrict__ wv16,
    __half* __restrict__ woh16, __half* __restrict__ wol16)
{
    long i = (long)blockIdx.x * 256 + threadIdx.x;   // < 3145728
    const float* src; bf16 *h = nullptr, *l = nullptr;
    __half *f16 = nullptr, *f16h = nullptr, *f16l = nullptr;
    long li;
    if (i < 1048576)      { src = s0; h = h0; l = l0; li = i; }
    else if (i < 2097152) { src = s1; h = h1; l = l1; f16 = x16; li = i - 1048576; }
    else {
        long j = i - 2097152;
        int w = (int)(j >> 18);
        li = j & 262143;
        if (w == 0)      { src = s2; h = h2; l = l2; }
        else if (w == 1) { src = s3; h = h3; l = l3; }
        else if (w == 2) { src = s4; f16 = wv16; }
        else             { src = s5; f16h = woh16; f16l = wol16; }
    }
    float4 v = ((const float4*)src)[li];
    float f[4] = {v.x, v.y, v.z, v.w};
    if (h) {
        __align__(8) bf16 hv[4], lv[4];
#pragma unroll
        for (int j = 0; j < 4; j++) {
            hv[j] = __float2bfloat16(f[j]);
            lv[j] = __float2bfloat16(f[j] - __bfloat162float(hv[j]));
        }
        ((uint2*)h)[li] = *(uint2*)hv;
        ((uint2*)l)[li] = *(uint2*)lv;
    }
    if (f16) {
        __align__(8) __half g16[4];
#pragma unroll
        for (int j = 0; j < 4; j++) g16[j] = __float2half_rn(f[j]);
        ((uint2*)f16)[li] = *(uint2*)g16;
    }
    if (f16h) {
        __align__(8) __half hv[4], lv[4];
#pragma unroll
        for (int j = 0; j < 4; j++) {
            float fs = f[j] * 64.0f;                 // scale keeps lo in normal fp16 range
            hv[j] = __float2half_rn(fs);
            lv[j] = __float2half_rn(fs - __half2float(hv[j]));
        }
        ((uint2*)f16h)[li] = *(uint2*)hv;
        ((uint2*)f16l)[li] = *(uint2*)lv;
    }
}

// ---------------------------------------------------------------------------
// hgemm body (bf16x3, proven) — used for Q/K projections
// ---------------------------------------------------------------------------
static __device__ __forceinline__ void hgemm_body(
    const bf16* __restrict__ Ah, const bf16* __restrict__ Al,
    const bf16* __restrict__ Bh, const bf16* __restrict__ Bl,
    const float* __restrict__ bias,
    bf16* __restrict__ Ch, bf16* __restrict__ Cl,
    int lda, int ldb, int ldc, char* sm)
{
    uint32_t sb = smem_u32(sm);
    int t = threadIdx.x, lane = t & 31, wid = t >> 5;
    int wm = wid & 3, wn = wid >> 2;
    long m0 = blockIdx.y * 128, n0 = blockIdx.x * 128;

    const bf16* g0 = Ah + m0 * lda;
    const bf16* g1 = Al + m0 * lda;
    const bf16* g2 = Bh + n0 * ldb;
    const bf16* g3 = Bl + n0 * ldb;

#define G_ISSUE(c_, buf_) do {                                                  \
    int _c = (c_); uint32_t _bs = sb + (buf_) * 40960;                          \
    _Pragma("unroll")                                                           \
    for (int i = 0; i < 8; i++) {                                               \
        const int tile = i >> 1;                                                \
        int w = t + 256 * (i & 1);                                               \
        int row = w >> 2, sg = w & 3;                                           \
        const bf16* gp = (tile == 0 ? g0 : tile == 1 ? g1 : tile == 2 ? g2 : g3)\
            + (long)row * (tile < 2 ? lda : ldb) + _c * 32 + sg * 8;            \
        CP16(_bs + tile * 10240 + row * 80 + sg * 16, gp);                      \
    }                                                                           \
    CPCOMMIT();                                                                 \
} while (0)

    float acc[2][8][4] = {};
    G_ISSUE(0, 0);
    G_ISSUE(1, 1);
    for (int c = 0; c < 32; c++) {
        if (c + 1 < 32) { CPWAIT(1); } else { CPWAIT(0); }
        __syncthreads();
        uint32_t bAh = sb + (c & 1) * 40960, bAl = bAh + 10240;
        uint32_t bBh = bAh + 20480, bBl = bAh + 30720;
#pragma unroll
        for (int k0 = 0; k0 < 32; k0 += 16) {
            uint32_t ah[2][4], al[2][4], bhf[4][4], blf[4][4];
#pragma unroll
            for (int mt = 0; mt < 2; mt++) {
                ldsmA(ah[mt], bAh, wm * 32 + mt * 16, k0, 80, lane);
                ldsmA(al[mt], bAl, wm * 32 + mt * 16, k0, 80, lane);
            }
#pragma unroll
            for (int p = 0; p < 4; p++) {
                ldsmB(bhf[p], bBh, wn * 64 + p * 16, k0, 80, lane);
                ldsmB(blf[p], bBl, wn * 64 + p * 16, k0, 80, lane);
            }
#pragma unroll
            for (int mt = 0; mt < 2; mt++)
#pragma unroll
                for (int p = 0; p < 4; p++) {
                    mma3(acc[mt][p * 2],     ah[mt], al[mt], &bhf[p][0], &blf[p][0]);
                    mma3(acc[mt][p * 2 + 1], ah[mt], al[mt], &bhf[p][2], &blf[p][2]);
                }
        }
        __syncthreads();
        if (c + 2 < 32) G_ISSUE(c + 2, c & 1);
    }
#undef G_ISSUE

#pragma unroll
    for (int mt = 0; mt < 2; mt++)
#pragma unroll
        for (int nt = 0; nt < 8; nt++) {
            float* cc = acc[mt][nt];
            long r0 = m0 + wm * 32 + mt * 16 + (lane >> 2);
            int col = (int)n0 + wn * 64 + nt * 8 + 2 * (lane & 3);
            float b0 = bias[col], b1 = bias[col + 1];
            store_split2(Ch, Cl, r0 * ldc + col, cc[0] + b0, cc[1] + b1);
            store_split2(Ch, Cl, (r0 + 8) * ldc + col, cc[2] + b0, cc[3] + b1);
        }
}

// projV body: V16 = x16 @ wv16^T + bv (fp16 single, fp32 accum)
static __device__ __forceinline__ void projV_body(
    const __half* __restrict__ x16, const __half* __restrict__ wv16,
    const float* __restrict__ bv, __half* __restrict__ V16, char* sm)
{
    uint32_t sb = smem_u32(sm);
    int t = threadIdx.x, lane = t & 31, wid = t >> 5;
    int wm = wid & 3, wn = wid >> 2;
    long m0 = blockIdx.y * 128, n0 = blockIdx.x * 128;

    const __half* gA = x16 + m0 * 1024;
    const __half* gB = wv16 + n0 * 1024;

#define GV_ISSUE(c_, buf_) do {                                                 \
    int _c = (c_); uint32_t _bs = sb + (buf_) * 20480;                          \
    _Pragma("unroll")                                                           \
    for (int i = 0; i < 4; i++) {                                               \
        int w = t + 256 * i;                                                    \
        int tile = w >> 9, inner = w & 511;                                     \
        int row = inner >> 2, sg = inner & 3;                                   \
        const __half* gp = (tile ? gB : gA) + (long)row * 1024 + _c * 32 + sg * 8; \
        CP16(_bs + tile * 10240 + row * 80 + sg * 16, gp);                      \
    }                                                                           \
    CPCOMMIT();                                                                 \
} while (0)

    float acc[2][8][4] = {};
    GV_ISSUE(0, 0);
    GV_ISSUE(1, 1);
    for (int c = 0; c < 32; c++) {
        if (c + 1 < 32) { CPWAIT(1); } else { CPWAIT(0); }
        __syncthreads();
        uint32_t bA = sb + (c & 1) * 20480, bB = bA + 10240;
#pragma unroll
        for (int k0 = 0; k0 < 32; k0 += 16) {
            uint32_t ah[2][4], bfr[4][4];
#pragma unroll
            for (int mt = 0; mt < 2; mt++)
                ldsmA(ah[mt], bA, wm * 32 + mt * 16, k0, 80, lane);
#pragma unroll
            for (int p = 0; p < 4; p++)
                ldsmB(bfr[p], bB, wn * 64 + p * 16, k0, 80, lane);
#pragma unroll
            for (int mt = 0; mt < 2; mt++)
#pragma unroll
                for (int p = 0; p < 4; p++) {
                    mma16816h(acc[mt][p * 2],     ah[mt], &bfr[p][0]);
                    mma16816h(acc[mt][p * 2 + 1], ah[mt], &bfr[p][2]);
                }
        }
        __syncthreads();
        if (c + 2 < 32) GV_ISSUE(c + 2, c & 1);
    }
#undef GV_ISSUE

#pragma unroll
    for (int mt = 0; mt < 2; mt++)
#pragma unroll
        for (int nt = 0; nt < 8; nt++) {
            float* cc = acc[mt][nt];
            long r0 = m0 + wm * 32 + mt * 16 + (lane >> 2);
            int col = (int)n0 + wn * 64 + nt * 8 + 2 * (lane & 3);
            float b0 = bv[col], b1 = bv[col + 1];
            __half2 v0 = __floats2half2_rn(cc[0] + b0, cc[1] + b1);
            __half2 v1 = __floats2half2_rn(cc[2] + b0, cc[3] + b1);
            *(uint32_t*)(V16 + r0 * 1024 + col)       = *(uint32_t*)&v0;
            *(uint32_t*)(V16 + (r0 + 8) * 1024 + col) = *(uint32_t*)&v1;
        }
}

// merged projections: z=0 Q (bf16x3), z=1 K (bf16x3), z=2 V (fp16)
__global__ __launch_bounds__(256) void proj_all(
    const bf16* __restrict__ qh, const bf16* __restrict__ ql,
    const bf16* __restrict__ xh, const bf16* __restrict__ xl,
    const __half* __restrict__ x16,
    const bf16* __restrict__ wqh, const bf16* __restrict__ wql,
    const bf16* __restrict__ wkh, const bf16* __restrict__ wkl,
    const __half* __restrict__ wv16,
    const float* __restrict__ bq, const float* __restrict__ bk, const float* __restrict__ bv,
    bf16* __restrict__ Qh, bf16* __restrict__ Ql,
    bf16* __restrict__ Kh, bf16* __restrict__ Kl,
    __half* __restrict__ V16)
{
    extern __shared__ char sm[];
    int z = blockIdx.z;
    if (z == 2) {
        projV_body(x16, wv16, bv, V16, sm);
    } else {
        const bf16* Ah = (z == 0) ? qh : xh;
        const bf16* Al = (z == 0) ? ql : xl;
        const bf16* Bh = (z == 0) ? wqh : wkh;
        const bf16* Bl = (z == 0) ? wql : wkl;
        const float* bias = (z == 0) ? bq : bk;
        bf16* Ch = (z == 0) ? Qh : Kh;
        bf16* Cl = (z == 0) ? Ql : Kl;
        hgemm_body(Ah, Al, Bh, Bl, bias, Ch, Cl, 1024, 1024, 1024, sm);
    }
}

// ---------------------------------------------------------------------------
// hgemm_out2: out = B16(fp16) @ (woh16+wol16)^T / 64 + bias  (2-product fp16)
// smem: buf b @ b*30720: A 10240 | Bh 10240 | Bl 10240  -> 61440B
// ---------------------------------------------------------------------------
__global__ __launch_bounds__(256) void hgemm_out2(
    const __half* __restrict__ A16,
    const __half* __restrict__ Bh16, const __half* __restrict__ Bl16,
    const float* __restrict__ bias, float* __restrict__ Cf)
{
    extern __shared__ char sm[];
    uint32_t sb = smem_u32(sm);
    int t = threadIdx.x, lane = t & 31, wid = t >> 5;
    int wm = wid & 3, wn = wid >> 2;
    long m0 = blockIdx.y * 128, n0 = blockIdx.x * 128;

    const __half* gA  = A16 + m0 * 1024;
    const __half* gBh = Bh16 + n0 * 1024;
    const __half* gBl = Bl16 + n0 * 1024;

#define GO_ISSUE(c_, buf_) do {                                                 \
    int _c = (c_); uint32_t _bs = sb + (buf_) * 30720;                          \
    _Pragma("unroll")                                                           \
    for (int i = 0; i < 6; i++) {                                               \
        int w = t + 256 * i;                                                    \
        int tile = w >> 9, inner = w & 511;                                     \
        int row = inner >> 2, sg = inner & 3;                                   \
        const __half* gp = (tile == 0 ? gA : tile == 1 ? gBh : gBl)             \
            + (long)row * 1024 + _c * 32 + sg * 8;                              \
        CP16(_bs + tile * 10240 + row * 80 + sg * 16, gp);                      \
    }                                                                           \
    CPCOMMIT();                                                                 \
} while (0)

    float acc[2][8][4] = {};
    GO_ISSUE(0, 0);
    GO_ISSUE(1, 1);
    for (int c = 0; c < 32; c++) {
        if (c + 1 < 32) { CPWAIT(1); } else { CPWAIT(0); }
        __syncthreads();
        uint32_t bA = sb + (c & 1) * 30720, bBh = bA + 10240, bBl = bA + 20480;
#pragma unroll
        for (int k0 = 0; k0 < 32; k0 += 16) {
            uint32_t ah[2][4], bhf[4][4], blf[4][4];
#pragma unroll
            for (int mt = 0; mt < 2; mt++)
                ldsmA(ah[mt], bA, wm * 32 + mt * 16, k0, 80, lane);
#pragma unroll
            for (int p = 0; p < 4; p++) {
                ldsmB(bhf[p], bBh, wn * 64 + p * 16, k0, 80, lane);
                ldsmB(blf[p], bBl, wn * 64 + p * 16, k0, 80, lane);
            }
#pragma unroll
            for (int mt = 0; mt < 2; mt++)
#pragma unroll
                for (int p = 0; p < 4; p++) {
                    mma16816h(acc[mt][p * 2],     ah[mt], &bhf[p][0]);
                    mma16816h(acc[mt][p * 2],     ah[mt], &blf[p][0]);
                    mma16816h(acc[mt][p * 2 + 1], ah[mt], &bhf[p][2]);
                    mma16816h(acc[mt][p * 2 + 1], ah[mt], &blf[p][2]);
                }
        }
        __syncthreads();
        if (c + 2 < 32) GO_ISSUE(c + 2, c & 1);
    }
#undef GO_ISSUE

    const float S = 0.015625f;   // 1/64 (wo was split pre-scaled by 64)
#pragma unroll
    for (int mt = 0; mt < 2; mt++)
#pragma unroll
        for (int nt = 0; nt < 8; nt++) {
            float* cc = acc[mt][nt];
            long r0 = m0 + wm * 32 + mt * 16 + (lane >> 2);
            int col = (int)n0 + wn * 64 + nt * 8 + 2 * (lane & 3);
            float b0 = bias[col], b1 = bias[col + 1];
            *(float2*)(Cf + r0 * 1024 + col) =
                make_float2(cc[0] * S + b0, cc[1] * S + b1);
            *(float2*)(Cf + (r0 + 8) * 1024 + col) =
                make_float2(cc[2] * S + b0, cc[3] * S + b1);
        }
}

// ---------------------------------------------------------------------------
// vtrans: V16 fp16 [4096 tok,1024] -> per (b,h) [64 d][2048 tok] (exact copy)
// ---------------------------------------------------------------------------
__global__ __launch_bounds__(256) void vtrans(
    const __half* __restrict__ V16, __half* __restrict__ Th) {
    __shared__ __half sh[64][72];
    int t = threadIdx.x, tt = blockIdx.x, bh = blockIdx.y;
    int b = bh >> 4, h = bh & 15;
    const __half* src = V16 + ((long)b * 2048 + tt * 64) * 1024 + h * 64;
#pragma unroll
    for (int i = 0; i < 2; i++) {
        int s = t + 256 * i, row = s >> 3, seg = s & 7;
        *(uint4*)&sh[row][seg * 8] = *(const uint4*)(src + (long)row * 1024 + seg * 8);
    }
    __syncthreads();
    __half* dh = Th + (long)bh * 64 * 2048 + tt * 64;
#pragma unroll
    for (int i = 0; i < 2; i++) {
        int s = t + 256 * i, d = s >> 3, seg = s & 7;
        __align__(16) __half th[8];
#pragma unroll
        for (int j = 0; j < 8; j++) th[j] = sh[seg * 8 + j][d];
        *(uint4*)(dh + (long)d * 2048 + seg * 8) = *(uint4*)th;
    }
}

// ---------------------------------------------------------------------------
// fused_attn — round-15 structure; only change: blended written as fp16 single
// ---------------------------------------------------------------------------
#define FQ_H  0
#define FQ_L  9216
#define FKBUF(b) (18432 + (b) * 18432)
#define FP_H  55296
#define FV_H  64512
#define FPART 73728
#define FINVS 74752
#define FMSK  75008
#define SM_FUSED 83200

__global__ __launch_bounds__(256, 2) void fused_attn(
    const bf16* __restrict__ Qh, const bf16* __restrict__ Ql,
    const bf16* __restrict__ Kh, const bf16* __restrict__ Kl,
    const __half* __restrict__ Vth,
    const float* __restrict__ mask,
    float* __restrict__ A, __half* __restrict__ B16)
{
    extern __shared__ char sm[];
    uint32_t sb = smem_u32(sm);
    int t = threadIdx.x, lane = t & 31, wid = t >> 5;
    int wm = wid & 1, wn = wid >> 1;          // 2m x 4n; warp tile 32q x 16k
    int qt = blockIdx.x, bh = blockIdx.y;
    int b = bh >> 4, h = bh & 15;

    const bf16* qh = Qh + ((long)b * 2048 + qt * 64) * 1024 + h * 64;
    const bf16* ql = Ql + ((long)b * 2048 + qt * 64) * 1024 + h * 64;
    const bf16* kh = Kh + (long)b * 2048 * 1024 + h * 64;
    const bf16* kl = Kl + (long)b * 2048 * 1024 + h * 64;
    const __half* vth = Vth + (long)bh * 64 * 2048;
    float* Abh = A + ((long)bh * 2048 + qt * 64) * 2048;
    const float* mrow = mask + (long)b * 2048;

    float* part  = (float*)(sm + FPART);
    float* linvs = (float*)(sm + FINVS);
    float* msk   = (float*)(sm + FMSK);

#define KISSUE(kt_, buf_) do {                                                   \
    int _kt = (kt_); uint32_t _kb = sb + FKBUF(buf_);                            \
    _Pragma("unroll")                                                            \
    for (int i = 0; i < 4; i++) {                                                \
        int w = t + 256 * i;                                                     \
        int tile = w >> 9, inner = w & 511;                                      \
        int row = inner >> 3, sg = inner & 7;                                    \
        const bf16* src = (tile ? kl : kh) + (long)(_kt * 64 + row) * 1024 + sg * 8; \
        CP16(_kb + tile * 9216 + row * 144 + sg * 16, src);                      \
    }                                                                            \
    CPCOMMIT();                                                                  \
} while (0)

#define VISSUE(kt_) do {                                                         \
    int _kt = (kt_);                                                             \
    _Pragma("unroll")                                                            \
    for (int i = 0; i < 2; i++) {                                                \
        int w = t + 256 * i;                                                     \
        int row = w >> 3, sg = w & 7;                                            \
        const __half* src = vth + (long)row * 2048 + _kt * 64 + sg * 8;          \
        CP16(sb + FV_H + row * 144 + sg * 16, src);                              \
    }                                                                            \
    CPCOMMIT();                                                                  \
} while (0)

    // prologue
    KISSUE(0, 0);
#pragma unroll
    for (int i = 0; i < 4; i++) {
        int w = t + 256 * i;
        int tile = w >> 9, inner = w & 511;
        int row = inner >> 3, sg = inner & 7;
        const bf16* src = (tile ? ql : qh) + (long)row * 1024 + sg * 8;
        *(uint4*)(sm + (tile ? FQ_L : FQ_H) + row * 144 + sg * 16) = *(const uint4*)src;
    }
#pragma unroll
    for (int j = 0; j < 8; j++) {
        int idx = t + 256 * j;
        msk[idx] = (1.0f - mrow[idx]) * (-1e9f);
    }
    __syncthreads();

    uint32_t qfh[2][4][4], qfl[2][4][4];
#pragma unroll
    for (int mt = 0; mt < 2; mt++)
#pragma unroll
        for (int k4 = 0; k4 < 4; k4++) {
            ldsmA(qfh[mt][k4], sb + FQ_H, wm * 32 + mt * 16, k4 * 16, 144, lane);
            ldsmA(qfl[mt][k4], sb + FQ_L, wm * 32 + mt * 16, k4 * 16, 144, lane);
        }

    // pass A: rowsum
    float rs[4] = {0.f, 0.f, 0.f, 0.f};
    for (int kt = 0; kt < 32; kt++) {
        CPWAIT(0);
        __syncthreads();
        if (kt + 1 < 32) KISSUE(kt + 1, (kt + 1) & 1);

        uint32_t kb = sb + FKBUF(kt & 1);
        float acc[2][2][4] = {};
#pragma unroll
        for (int k4 = 0; k4 < 4; k4++) {
            uint32_t bhf[4], blf[4];
            ldsmB(bhf, kb,        wn * 16, k4 * 16, 144, lane);
            ldsmB(blf, kb + 9216, wn * 16, k4 * 16, 144, lane);
#pragma unroll
            for (int mt = 0; mt < 2; mt++) {
                mma3(acc[mt][0], qfh[mt][k4], qfl[mt][k4], &bhf[0], &blf[0]);
                mma3(acc[mt][1], qfh[mt][k4], qfl[mt][k4], &bhf[2], &blf[2]);
            }
        }
#pragma unroll
        for (int nt = 0; nt < 2; nt++) {
            int cl = kt * 64 + wn * 16 + nt * 8 + 2 * (lane & 3);
            float m0v = msk[cl], m1v = msk[cl + 1];
#pragma unroll
            for (int mt = 0; mt < 2; mt++) {
                float* cc = acc[mt][nt];
                rs[mt * 2 + 0] += __expf(cc[0] + m0v) + __expf(cc[1] + m1v);
                rs[mt * 2 + 1] += __expf(cc[2] + m0v) + __expf(cc[3] + m1v);
            }
        }
    }

    KISSUE(0, 0);

#pragma unroll
    for (int i = 0; i < 4; i++) {
        rs[i] += __shfl_xor_sync(0xffffffffu, rs[i], 1);
        rs[i] += __shfl_xor_sync(0xffffffffu, rs[i], 2);
    }
    __syncthreads();
    if ((lane & 3) == 0) {
#pragma unroll
        for (int mt = 0; mt < 2; mt++)
#pragma unroll
            for (int hf = 0; hf < 2; hf++)
                part[wn * 64 + wm * 32 + mt * 16 + hf * 8 + (lane >> 2)] = rs[mt * 2 + hf];
    }
    __syncthreads();
    if (t < 64)
        linvs[t] = -__logf(part[t] + part[64 + t] + part[128 + t] + part[192 + t]);
    __syncthreads();

    float linvr[2][2];
#pragma unroll
    for (int mt = 0; mt < 2; mt++) {
        linvr[mt][0] = linvs[wm * 32 + mt * 16 + (lane >> 2)];
        linvr[mt][1] = linvs[wm * 32 + mt * 16 + 8 + (lane >> 2)];
    }

    // pass B
    float oacc[2][2][4] = {};
    for (int kt = 0; kt < 32; kt++) {
        CPWAIT(0);
        __syncthreads();
        VISSUE(kt);
        if (kt + 1 < 32) KISSUE(kt + 1, (kt + 1) & 1);

        uint32_t kb = sb + FKBUF(kt & 1);
        float acc[2][2][4] = {};
#pragma unroll
        for (int k4 = 0; k4 < 4; k4++) {
            uint32_t bhf[4], blf[4];
            ldsmB(bhf, kb,        wn * 16, k4 * 16, 144, lane);
            ldsmB(blf, kb + 9216, wn * 16, k4 * 16, 144, lane);
#pragma unroll
            for (int mt = 0; mt < 2; mt++) {
                mma3(acc[mt][0], qfh[mt][k4], qfl[mt][k4], &bhf[0], &blf[0]);
                mma3(acc[mt][1], qfh[mt][k4], qfl[mt][k4], &bhf[2], &blf[2]);
            }
        }

#pragma unroll
        for (int nt = 0; nt < 2; nt++) {
            int cl = wn * 16 + nt * 8 + 2 * (lane & 3);
            int gc = kt * 64 + cl;
            float m0v = msk[gc], m1v = msk[gc + 1];
#pragma unroll
            for (int mt = 0; mt < 2; mt++) {
                float* cc = acc[mt][nt];
                int r0 = wm * 32 + mt * 16 + (lane >> 2);
                float e0 = __expf(cc[0] + m0v + linvr[mt][0]);
                float e1 = __expf(cc[1] + m1v + linvr[mt][0]);
                float e2 = __expf(cc[2] + m0v + linvr[mt][1]);
                float e3 = __expf(cc[3] + m1v + linvr[mt][1]);
                *(float2*)(Abh + (long)r0 * 2048 + gc)       = make_float2(e0, e1);
                *(float2*)(Abh + (long)(r0 + 8) * 2048 + gc) = make_float2(e2, e3);
                smem_h2f16(sm + FP_H + r0 * 144 + cl * 2, e0, e1);
                smem_h2f16(sm + FP_H + (r0 + 8) * 144 + cl * 2, e2, e3);
            }
        }

        if (kt + 1 < 32) { CPWAIT(1); } else { CPWAIT(0); }
        __syncthreads();

#pragma unroll
        for (int k4 = 0; k4 < 4; k4++) {
            uint32_t ah[2][4], bhf[4];
#pragma unroll
            for (int mt = 0; mt < 2; mt++)
                ldsmA(ah[mt], sb + FP_H, wm * 32 + mt * 16, k4 * 16, 144, lane);
            ldsmB(bhf, sb + FV_H, wn * 16, k4 * 16, 144, lane);
#pragma unroll
            for (int mt = 0; mt < 2; mt++) {
                mma16816h(oacc[mt][0], ah[mt], &bhf[0]);
                mma16816h(oacc[mt][1], ah[mt], &bhf[2]);
            }
        }
    }

    // write blended fp16 [b, q, h*64+d]
#pragma unroll
    for (int mt = 0; mt < 2; mt++)
#pragma unroll
        for (int nt = 0; nt < 2; nt++) {
            float* cc = oacc[mt][nt];
            long r0 = (long)b * 2048 + qt * 64 + wm * 32 + mt * 16 + (lane >> 2);
            int col = h * 64 + wn * 16 + nt * 8 + 2 * (lane & 3);
            __half2 v0 = __floats2half2_rn(cc[0], cc[1]);
            __half2 v1 = __floats2half2_rn(cc[2], cc[3]);
            *(uint32_t*)(B16 + r0 * 1024 + col)       = *(uint32_t*)&v0;
            *(uint32_t*)(B16 + (r0 + 8) * 1024 + col) = *(uint32_t*)&v1;
        }
}

// ===========================================================================
extern "C" void kernel_launch(void* const* d_in, const int* in_sizes, int n_in,
                              void* d_out, int out_size) {
    (void)in_sizes; (void)n_in;
    const float* query        = (const float*)d_in[0];
    const float* input_embeds = (const float*)d_in[1];
    const float* mask         = (const float*)d_in[2];
    const float* wq_w = (const float*)d_in[3];
    const float* wq_b = (const float*)d_in[4];
    const float* wk_w = (const float*)d_in[5];
    const float* wk_b = (const float*)d_in[6];
    const float* wv_w = (const float*)d_in[7];
    const float* wv_b = (const float*)d_in[8];
    const float* wo_w = (const float*)d_in[9];
    const float* wo_b = (const float*)d_in[10];
    float* out = (float*)d_out;

    bf16 *qh, *ql, *xh, *xl, *wqh, *wql, *wkh, *wkl;
    bf16 *Qh, *Ql, *Kh, *Kl;
    __half *x16, *wv16, *woh16, *wol16, *V16, *Vth16, *B16;
    float *attn_scratch;
    cudaGetSymbolAddress((void**)&qh, g_qh);   cudaGetSymbolAddress((void**)&ql, g_ql);
    cudaGetSymbolAddress((void**)&xh, g_xh);   cudaGetSymbolAddress((void**)&xl, g_xl);
    cudaGetSymbolAddress((void**)&x16, g_x16);
    cudaGetSymbolAddress((void**)&wqh, g_wqh); cudaGetSymbolAddress((void**)&wql, g_wql);
    cudaGetSymbolAddress((void**)&wkh, g_wkh); cudaGetSymbolAddress((void**)&wkl, g_wkl);
    cudaGetSymbolAddress((void**)&wv16, g_wv16);
    cudaGetSymbolAddress((void**)&woh16, g_woh16);
    cudaGetSymbolAddress((void**)&wol16, g_wol16);
    cudaGetSymbolAddress((void**)&Qh, g_Qh);   cudaGetSymbolAddress((void**)&Ql, g_Ql);
    cudaGetSymbolAddress((void**)&Kh, g_Kh);   cudaGetSymbolAddress((void**)&Kl, g_Kl);
    cudaGetSymbolAddress((void**)&V16, g_V16);
    cudaGetSymbolAddress((void**)&Vth16, g_Vth16);
    cudaGetSymbolAddress((void**)&B16, g_B16);
    cudaGetSymbolAddress((void**)&attn_scratch, g_attn);

    const long OUT_E = 4194304L, ATTN_E = 134217728L;
    float* attn = ((long)out_size >= OUT_E + ATTN_E) ? (out + OUT_E) : attn_scratch;

    const int SM_GEMM = 81920, SM_OUT = 61440;
    cudaFuncSetAttribute(proj_all,   cudaFuncAttributeMaxDynamicSharedMemorySize, SM_GEMM);
    cudaFuncSetAttribute(hgemm_out2, cudaFuncAttributeMaxDynamicSharedMemorySize, SM_OUT);
    cudaFuncSetAttribute(fused_attn, cudaFuncAttributeMaxDynamicSharedMemorySize, SM_FUSED);

    cvt_all<<<12288, 256>>>(query, input_embeds, wq_w, wk_w, wv_w, wo_w,
                            qh, ql, xh, xl, x16, wqh, wql, wkh, wkl,
                            wv16, woh16, wol16);

    proj_all<<<dim3(8, 32, 3), 256, SM_GEMM>>>(qh, ql, xh, xl, x16,
                                               wqh, wql, wkh, wkl, wv16,
                                               wq_b, wk_b, wv_b,
                                               Qh, Ql, Kh, Kl, V16);

    vtrans<<<dim3(32, 32), 256>>>(V16, Vth16);

    fused_attn<<<dim3(32, 32), 256, SM_FUSED>>>(Qh, Ql, Kh, Kl, Vth16, mask,
                                                attn, B16);

    hgemm_out2<<<dim3(8, 32), 256, SM_OUT>>>(B16, woh16, wol16, wo_b, out);
}